// round 3
// baseline (speedup 1.0000x reference)
#include <cuda_runtime.h>
#include <cstdint>

#define NN 100000
#define EE 1600000
#define KF 128

// ---------------- scratch (static device globals; no runtime alloc) ----------
__device__ __align__(16) float g_agg[(size_t)NN * 128];  // aggregation buffer
__device__ __align__(16) float g_h[(size_t)NN * 128];    // layer-1 output
__device__ __align__(16) float g_h2[(size_t)NN * 64];    // layer-2 output
__device__ int   g_deg[NN];        // in-degree (no self loop)
__device__ int   g_fill[NN];       // scatter cursor
__device__ int   g_off[NN + 1];    // CSR row offsets (by dst)
__device__ int   g_csrc[EE];       // CSR: source node of each incoming edge
__device__ float g_rcnt[NN];       // 1/max(deg,1)  (mean divisor)
__device__ float g_dis[NN];        // rsqrt(deg+1)  (GCN norm)

// ---------------- zero init (graph-safe) --------------------------------------
__global__ void zero_counts_kernel() {
    int v = blockIdx.x * blockDim.x + threadIdx.x;
    if (v < NN) { g_deg[v] = 0; g_fill[v] = 0; }
}

// ---------------- CSR build (edge_index is int32: JAX x64 disabled) -----------
__global__ void count_deg_kernel(const int* __restrict__ dst) {
    int e = blockIdx.x * blockDim.x + threadIdx.x;
    if (e < EE) {
        unsigned d = (unsigned)dst[e];
        if (d < NN) atomicAdd(&g_deg[d], 1);
    }
}

// single-block exclusive scan over g_deg -> g_off  (N = 100000, 1024 threads)
__global__ void scan_deg_kernel() {
    __shared__ int warp_sums[32];
    __shared__ int carry;
    const int tid = threadIdx.x, lane = tid & 31, wid = tid >> 5;
    if (tid == 0) carry = 0;
    __syncthreads();
    for (int base = 0; base < NN; base += 1024) {
        int i = base + tid;
        int v = (i < NN) ? g_deg[i] : 0;
        int inc = v;
        #pragma unroll
        for (int o = 1; o < 32; o <<= 1) {
            int t = __shfl_up_sync(0xffffffffu, inc, o);
            if (lane >= o) inc += t;
        }
        if (lane == 31) warp_sums[wid] = inc;
        __syncthreads();
        if (wid == 0) {
            int s = warp_sums[lane];
            #pragma unroll
            for (int o = 1; o < 32; o <<= 1) {
                int t = __shfl_up_sync(0xffffffffu, s, o);
                if (lane >= o) s += t;
            }
            warp_sums[lane] = s;
        }
        __syncthreads();
        int warp_off = (wid > 0) ? warp_sums[wid - 1] : 0;
        if (i < NN) g_off[i] = carry + warp_off + (inc - v);
        int total = warp_sums[31];
        __syncthreads();
        if (tid == 0) carry += total;
        __syncthreads();
    }
    if (threadIdx.x == 0) g_off[NN] = carry;
}

__global__ void build_csr_kernel(const int* __restrict__ src,
                                 const int* __restrict__ dst) {
    int e = blockIdx.x * blockDim.x + threadIdx.x;
    if (e >= EE) return;
    unsigned d = (unsigned)dst[e];
    unsigned s = (unsigned)src[e];
    if (d >= NN || s >= NN) return;
    int p = g_off[d] + atomicAdd(&g_fill[d], 1);
    g_csrc[p] = (int)s;
}

__global__ void prep_kernel() {
    int v = blockIdx.x * blockDim.x + threadIdx.x;
    if (v >= NN) return;
    float d = (float)g_deg[v];
    g_rcnt[v] = 1.0f / fmaxf(d, 1.0f);
    g_dis[v]  = rsqrtf(d + 1.0f);
}

// ---------------- aggregation: warp per node, 128 features (float4/lane) ------
// LAYER==1: feat = x (param), LAYER==2: feat = g_h. Output: g_agg.
template <int LAYER>
__global__ void csr_agg_kernel(const float* __restrict__ xin) {
    int v = blockIdx.x * (blockDim.x >> 5) + (threadIdx.x >> 5);
    if (v >= NN) return;
    const float* feat = (LAYER == 1) ? xin : (const float*)g_h;
    int lane = threadIdx.x & 31;
    int beg = g_off[v], end = g_off[v + 1];
    float4 acc = make_float4(0.f, 0.f, 0.f, 0.f);
    int j = beg;
    for (; j + 1 < end; j += 2) {
        int s0 = g_csrc[j], s1 = g_csrc[j + 1];
        float4 t0 = ((const float4*)(feat + (size_t)s0 * 128))[lane];
        float4 t1 = ((const float4*)(feat + (size_t)s1 * 128))[lane];
        acc.x += t0.x + t1.x; acc.y += t0.y + t1.y;
        acc.z += t0.z + t1.z; acc.w += t0.w + t1.w;
    }
    if (j < end) {
        int s = g_csrc[j];
        float4 t = ((const float4*)(feat + (size_t)s * 128))[lane];
        acc.x += t.x; acc.y += t.y; acc.z += t.z; acc.w += t.w;
    }
    ((float4*)(g_agg + (size_t)v * 128))[lane] = acc;
}

// ---------------- fused linear: out = relu?(rcnt[r]*agg @ Wl^T + X @ Wr^T + b) -
// LAYER==1: A=g_agg, X=x(param), out=g_h, BN=128, RELU
// LAYER==2: A=g_agg, X=g_h,      out=g_h2, BN=64
template <int LAYER, int BN, int TM, int TN, bool RELU>
__global__ void __launch_bounds__(256)
fused_linear(const float* __restrict__ xin,
             const float* __restrict__ Wl, const float* __restrict__ Wr,
             const float* __restrict__ bias) {
    constexpr int K = KF;
    constexpr int BK = 16;
    constexpr int THR_C = BN / TN;       // 16
    constexpr int THR_R = 256 / THR_C;   // 16
    constexpr int BM = THR_R * TM;       // 128
    constexpr int LDA = BM + 4;
    constexpr int LDW = BN + 4;
    __shared__ float sA[BK][LDA];
    __shared__ float sX[BK][LDA];
    __shared__ float sWl[BK][LDW];
    __shared__ float sWr[BK][LDW];

    const float* A = (const float*)g_agg;
    const float* X = (LAYER == 1) ? xin : (const float*)g_h;
    float* out = (LAYER == 1) ? (float*)g_h : (float*)g_h2;

    const int tid = threadIdx.x;
    const int row0 = blockIdx.x * BM;
    const int tc = tid % THR_C;
    const int tr = tid / THR_C;
    const int r0 = tr * TM;
    const int c0 = tc * TN;

    float acc[TM][TN];
    #pragma unroll
    for (int i = 0; i < TM; i++)
        #pragma unroll
        for (int j = 0; j < TN; j++) acc[i][j] = 0.f;

    for (int k0 = 0; k0 < K; k0 += BK) {
        #pragma unroll
        for (int i = tid; i < BM * BK; i += 256) {
            int m = i >> 4, k = i & 15;
            int gr = row0 + m;
            float a = 0.f, xx = 0.f;
            if (gr < NN) {
                a  = A[(size_t)gr * K + k0 + k] * g_rcnt[gr];
                xx = X[(size_t)gr * K + k0 + k];
            }
            sA[k][m] = a;
            sX[k][m] = xx;
        }
        #pragma unroll
        for (int i = tid; i < BN * BK; i += 256) {
            int c = i >> 4, k = i & 15;
            sWl[k][c] = Wl[(size_t)c * K + k0 + k];
            sWr[k][c] = Wr[(size_t)c * K + k0 + k];
        }
        __syncthreads();
        #pragma unroll
        for (int k = 0; k < BK; k++) {
            float af[TM], xf[TM], wl[TN], wr[TN];
            #pragma unroll
            for (int i = 0; i < TM; i += 4) {
                *(float4*)&af[i] = *(const float4*)&sA[k][r0 + i];
                *(float4*)&xf[i] = *(const float4*)&sX[k][r0 + i];
            }
            #pragma unroll
            for (int j = 0; j < TN; j += 4) {
                *(float4*)&wl[j] = *(const float4*)&sWl[k][c0 + j];
                *(float4*)&wr[j] = *(const float4*)&sWr[k][c0 + j];
            }
            #pragma unroll
            for (int i = 0; i < TM; i++)
                #pragma unroll
                for (int j = 0; j < TN; j++)
                    acc[i][j] += af[i] * wl[j] + xf[i] * wr[j];
        }
        __syncthreads();
    }
    #pragma unroll
    for (int i = 0; i < TM; i++) {
        int gr = row0 + r0 + i;
        if (gr >= NN) continue;
        #pragma unroll
        for (int j = 0; j < TN; j++) {
            float v = acc[i][j] + bias[c0 + j];
            if (RELU) v = fmaxf(v, 0.f);
            out[(size_t)gr * BN + c0 + j] = v;
        }
    }
}

// ---------------- GCN propagation: warp per node, 64 features (float2/lane) ---
__global__ void iconv_kernel(float* __restrict__ out) {
    int v = blockIdx.x * (blockDim.x >> 5) + (threadIdx.x >> 5);
    if (v >= NN) return;
    const float* h2 = (const float*)g_h2;
    int lane = threadIdx.x & 31;
    float dv = g_dis[v];
    float2 hv = ((const float2*)(h2 + (size_t)v * 64))[lane];
    float accx = dv * hv.x, accy = dv * hv.y;  // self loop (outer dv applied at end)
    int beg = g_off[v], end = g_off[v + 1];
    int j = beg;
    for (; j + 1 < end; j += 2) {
        int s0 = g_csrc[j], s1 = g_csrc[j + 1];
        float d0 = g_dis[s0], d1 = g_dis[s1];
        float2 t0 = ((const float2*)(h2 + (size_t)s0 * 64))[lane];
        float2 t1 = ((const float2*)(h2 + (size_t)s1 * 64))[lane];
        accx += d0 * t0.x + d1 * t1.x;
        accy += d0 * t0.y + d1 * t1.y;
    }
    if (j < end) {
        int s = g_csrc[j];
        float ds = g_dis[s];
        float2 t = ((const float2*)(h2 + (size_t)s * 64))[lane];
        accx += ds * t.x; accy += ds * t.y;
    }
    float2 r;
    r.x = dv * accx;
    r.y = dv * accy;
    ((float2*)(out + (size_t)v * 64))[lane] = r;
}

// ---------------- launcher (kernel launches ONLY) ------------------------------
extern "C" void kernel_launch(void* const* d_in, const int* in_sizes, int n_in,
                              void* d_out, int out_size) {
    const float* x   = (const float*)d_in[0];
    const int*   ei  = (const int*)d_in[1];   // int32: JAX default has x64 disabled
    const float* W1l = (const float*)d_in[2];
    const float* b1  = (const float*)d_in[3];
    const float* W1r = (const float*)d_in[4];
    const float* W2l = (const float*)d_in[5];
    const float* b2  = (const float*)d_in[6];
    const float* W2r = (const float*)d_in[7];
    float* out = (float*)d_out;

    const int* src = ei;
    const int* dst = ei + EE;

    const int EB = (EE + 255) / 256;
    const int NB = (NN + 255) / 256;

    zero_counts_kernel<<<NB, 256>>>();
    count_deg_kernel<<<EB, 256>>>(dst);
    scan_deg_kernel<<<1, 1024>>>();
    build_csr_kernel<<<EB, 256>>>(src, dst);
    prep_kernel<<<NB, 256>>>();

    const int WARP_GRID = (NN + 7) / 8;   // 8 warps (nodes) per 256-thread block
    const int GEMM_GRID = (NN + 127) / 128;

    // layer 1: h = relu(mean_agg(x) @ W1l^T + b1 + x @ W1r^T)
    csr_agg_kernel<1><<<WARP_GRID, 256>>>(x);
    fused_linear<1, 128, 8, 8, true><<<GEMM_GRID, 256>>>(x, W1l, W1r, b1);

    // layer 2: h2 = mean_agg(h) @ W2l^T + b2 + h @ W2r^T
    csr_agg_kernel<2><<<WARP_GRID, 256>>>(x);
    fused_linear<2, 64, 8, 4, false><<<GEMM_GRID, 256>>>(x, W2l, W2r, b2);

    // iconv: out = D^-1/2 (A+I) D^-1/2 h2
    iconv_kernel<<<WARP_GRID, 256>>>(out);
}

// round 4
// speedup vs baseline: 1.2303x; 1.2303x over previous
#include <cuda_runtime.h>
#include <cstdint>

#define NN 100000
#define EE 1600000
#define KF 128

// ---------------- scratch (static device globals; no runtime alloc) ----------
__device__ __align__(16) float g_p[(size_t)NN * 128];   // X @ Wl^T   (layer1: 128, layer2: 64 packed stride 64)
__device__ __align__(16) float g_r[(size_t)NN * 128];   // X @ Wr^T+b (same packing)
__device__ __align__(16) float g_h[(size_t)NN * 128];   // layer-1 output
__device__ __align__(16) float g_h2[(size_t)NN * 64];   // layer-2 output
__device__ int   g_deg[NN];
__device__ int   g_fill[NN];
__device__ int   g_off[NN + 1];
__device__ int   g_csrc[EE];
__device__ float g_rcnt[NN];       // 1/max(deg,1)
__device__ float g_dis[NN];        // rsqrt(deg+1)

// ---------------- packed fp32x2 helpers (sm_103a) ------------------------------
__device__ __forceinline__ unsigned long long pk2(float lo, float hi) {
    unsigned long long r;
    asm("mov.b64 %0, {%1, %2};" : "=l"(r) : "f"(lo), "f"(hi));
    return r;
}
__device__ __forceinline__ void upk2(float& lo, float& hi, unsigned long long v) {
    asm("mov.b64 {%0, %1}, %2;" : "=f"(lo), "=f"(hi) : "l"(v));
}
__device__ __forceinline__ void ffma2(unsigned long long& d, unsigned long long a,
                                      unsigned long long b) {
    asm("fma.rn.f32x2 %0, %1, %2, %0;" : "+l"(d) : "l"(a), "l"(b));
}

// ---------------- init + CSR build ---------------------------------------------
__global__ void zero_counts_kernel() {
    int v = blockIdx.x * blockDim.x + threadIdx.x;
    if (v < NN) { g_deg[v] = 0; g_fill[v] = 0; }
}

__global__ void count_deg_kernel(const int4* __restrict__ dst4) {
    int e = blockIdx.x * blockDim.x + threadIdx.x;
    if (e < EE / 4) {
        int4 d = dst4[e];
        if ((unsigned)d.x < NN) atomicAdd(&g_deg[d.x], 1);
        if ((unsigned)d.y < NN) atomicAdd(&g_deg[d.y], 1);
        if ((unsigned)d.z < NN) atomicAdd(&g_deg[d.z], 1);
        if ((unsigned)d.w < NN) atomicAdd(&g_deg[d.w], 1);
    }
}

// single-block exclusive scan over g_deg -> g_off
__global__ void scan_deg_kernel() {
    __shared__ int warp_sums[32];
    __shared__ int carry;
    const int tid = threadIdx.x, lane = tid & 31, wid = tid >> 5;
    if (tid == 0) carry = 0;
    __syncthreads();
    for (int base = 0; base < NN; base += 1024) {
        int i = base + tid;
        int v = (i < NN) ? g_deg[i] : 0;
        int inc = v;
        #pragma unroll
        for (int o = 1; o < 32; o <<= 1) {
            int t = __shfl_up_sync(0xffffffffu, inc, o);
            if (lane >= o) inc += t;
        }
        if (lane == 31) warp_sums[wid] = inc;
        __syncthreads();
        if (wid == 0) {
            int s = warp_sums[lane];
            #pragma unroll
            for (int o = 1; o < 32; o <<= 1) {
                int t = __shfl_up_sync(0xffffffffu, s, o);
                if (lane >= o) s += t;
            }
            warp_sums[lane] = s;
        }
        __syncthreads();
        int warp_off = (wid > 0) ? warp_sums[wid - 1] : 0;
        if (i < NN) g_off[i] = carry + warp_off + (inc - v);
        int total = warp_sums[31];
        __syncthreads();
        if (tid == 0) carry += total;
        __syncthreads();
    }
    if (threadIdx.x == 0) g_off[NN] = carry;
}

__global__ void build_csr_kernel(const int* __restrict__ src,
                                 const int* __restrict__ dst) {
    int e = blockIdx.x * blockDim.x + threadIdx.x;
    if (e >= EE) return;
    unsigned d = (unsigned)dst[e];
    unsigned s = (unsigned)src[e];
    if (d >= NN || s >= NN) return;
    int p = g_off[d] + atomicAdd(&g_fill[d], 1);
    g_csrc[p] = (int)s;
}

__global__ void prep_kernel() {
    int v = blockIdx.x * blockDim.x + threadIdx.x;
    if (v >= NN) return;
    float d = (float)g_deg[v];
    g_rcnt[v] = 1.0f / fmaxf(d, 1.0f);
    g_dis[v]  = rsqrtf(d + 1.0f);
}

// ---------------- dual GEMM: P = X@Wl^T, R = X@Wr^T + b  (f32x2 packed FMA) ----
// LAYER==1: X = xin (stride 128), BNH=128, BM=64
// LAYER==2: X = g_h (stride 128), BNH=64,  BM=128
template <int LAYER, int BNH, int BM>
__global__ void __launch_bounds__(256)
gemm_dual(const float* __restrict__ xin,
          const float* __restrict__ Wl, const float* __restrict__ Wr,
          const float* __restrict__ bias) {
    constexpr int K = KF;
    constexpr int BK = 16;
    constexpr int N2 = 2 * BNH;
    constexpr int TN = 8;
    constexpr int THR_C = N2 / TN;
    constexpr int THR_R = 256 / THR_C;
    constexpr int TM = BM / THR_R;     // == 8
    constexpr int LDA = BM + 4;
    constexpr int LDW = N2 + 4;
    __shared__ float sX[BK][LDA];
    __shared__ float sW[BK][LDW];

    const float* X = (LAYER == 1) ? xin : (const float*)g_h;
    float* P = (float*)g_p;
    float* R = (float*)g_r;

    const int tid = threadIdx.x;
    const int row0 = blockIdx.x * BM;
    const int tc = tid % THR_C;
    const int tr = tid / THR_C;
    const int r0 = tr * TM;
    const int c0 = tc * TN;

    unsigned long long acc[TM][TN / 2];
    #pragma unroll
    for (int i = 0; i < TM; i++)
        #pragma unroll
        for (int j = 0; j < TN / 2; j++) acc[i][j] = 0ull;

    for (int k0 = 0; k0 < K; k0 += BK) {
        #pragma unroll
        for (int i = tid; i < BM * BK; i += 256) {
            int m = i >> 4, k = i & 15;
            int gr = row0 + m;
            sX[k][m] = (gr < NN) ? X[(size_t)gr * K + k0 + k] : 0.f;
        }
        #pragma unroll
        for (int i = tid; i < N2 * BK; i += 256) {
            int c = i >> 4, k = i & 15;
            sW[k][c] = (c < BNH) ? Wl[(size_t)c * K + k0 + k]
                                 : Wr[(size_t)(c - BNH) * K + k0 + k];
        }
        __syncthreads();
        #pragma unroll
        for (int k = 0; k < BK; k++) {
            float af[TM];
            #pragma unroll
            for (int i = 0; i < TM; i += 4)
                *(float4*)&af[i] = *(const float4*)&sX[k][r0 + i];
            ulonglong2 w01 = *(const ulonglong2*)&sW[k][c0];
            ulonglong2 w23 = *(const ulonglong2*)&sW[k][c0 + 4];
            unsigned long long wq[4] = {w01.x, w01.y, w23.x, w23.y};
            #pragma unroll
            for (int i = 0; i < TM; i++) {
                unsigned long long ap = pk2(af[i], af[i]);
                #pragma unroll
                for (int j = 0; j < TN / 2; j++) ffma2(acc[i][j], ap, wq[j]);
            }
        }
        __syncthreads();
    }

    const bool isP = (c0 < BNH);
    const int  cc  = isP ? c0 : (c0 - BNH);
    float* dstb = isP ? P : R;
    float bj[TN];
    #pragma unroll
    for (int j = 0; j < TN; j++) bj[j] = isP ? 0.f : bias[cc + j];

    #pragma unroll
    for (int i = 0; i < TM; i++) {
        int gr = row0 + r0 + i;
        if (gr >= NN) continue;
        float o[TN];
        #pragma unroll
        for (int j = 0; j < TN / 2; j++) {
            float lo, hi;
            upk2(lo, hi, acc[i][j]);
            o[2 * j]     = lo + bj[2 * j];
            o[2 * j + 1] = hi + bj[2 * j + 1];
        }
        *(float4*)&dstb[(size_t)gr * BNH + cc]     = *(float4*)&o[0];
        *(float4*)&dstb[(size_t)gr * BNH + cc + 4] = *(float4*)&o[4];
    }
}

// ---------------- fused aggregation epilogues -----------------------------------
// h[v] = relu(rcnt[v] * sum_e P[src_e] + R[v])     (128 features, float4/lane)
__global__ void agg128_relu_kernel() {
    int v = blockIdx.x * (blockDim.x >> 5) + (threadIdx.x >> 5);
    if (v >= NN) return;
    int lane = threadIdx.x & 31;
    const float* P = (const float*)g_p;
    int beg = g_off[v], end = g_off[v + 1];
    float4 acc = make_float4(0.f, 0.f, 0.f, 0.f);
    int j = beg;
    for (; j + 3 < end; j += 4) {
        int s0 = g_csrc[j], s1 = g_csrc[j + 1], s2 = g_csrc[j + 2], s3 = g_csrc[j + 3];
        float4 t0 = ((const float4*)(P + (size_t)s0 * 128))[lane];
        float4 t1 = ((const float4*)(P + (size_t)s1 * 128))[lane];
        float4 t2 = ((const float4*)(P + (size_t)s2 * 128))[lane];
        float4 t3 = ((const float4*)(P + (size_t)s3 * 128))[lane];
        acc.x += (t0.x + t1.x) + (t2.x + t3.x);
        acc.y += (t0.y + t1.y) + (t2.y + t3.y);
        acc.z += (t0.z + t1.z) + (t2.z + t3.z);
        acc.w += (t0.w + t1.w) + (t2.w + t3.w);
    }
    for (; j < end; j++) {
        int s = g_csrc[j];
        float4 t = ((const float4*)(P + (size_t)s * 128))[lane];
        acc.x += t.x; acc.y += t.y; acc.z += t.z; acc.w += t.w;
    }
    float rc = g_rcnt[v];
    float4 rr = ((const float4*)(g_r + (size_t)v * 128))[lane];
    float4 o;
    o.x = fmaxf(fmaf(acc.x, rc, rr.x), 0.f);
    o.y = fmaxf(fmaf(acc.y, rc, rr.y), 0.f);
    o.z = fmaxf(fmaf(acc.z, rc, rr.z), 0.f);
    o.w = fmaxf(fmaf(acc.w, rc, rr.w), 0.f);
    ((float4*)(g_h + (size_t)v * 128))[lane] = o;
}

// h2[v] = rcnt[v] * sum_e P2[src_e] + R2[v]        (64 features, float2/lane)
__global__ void agg64_kernel() {
    int v = blockIdx.x * (blockDim.x >> 5) + (threadIdx.x >> 5);
    if (v >= NN) return;
    int lane = threadIdx.x & 31;
    const float* P = (const float*)g_p;   // packed stride 64
    int beg = g_off[v], end = g_off[v + 1];
    float ax = 0.f, ay = 0.f;
    int j = beg;
    for (; j + 3 < end; j += 4) {
        int s0 = g_csrc[j], s1 = g_csrc[j + 1], s2 = g_csrc[j + 2], s3 = g_csrc[j + 3];
        float2 t0 = ((const float2*)(P + (size_t)s0 * 64))[lane];
        float2 t1 = ((const float2*)(P + (size_t)s1 * 64))[lane];
        float2 t2 = ((const float2*)(P + (size_t)s2 * 64))[lane];
        float2 t3 = ((const float2*)(P + (size_t)s3 * 64))[lane];
        ax += (t0.x + t1.x) + (t2.x + t3.x);
        ay += (t0.y + t1.y) + (t2.y + t3.y);
    }
    for (; j < end; j++) {
        int s = g_csrc[j];
        float2 t = ((const float2*)(P + (size_t)s * 64))[lane];
        ax += t.x; ay += t.y;
    }
    float rc = g_rcnt[v];
    float2 rr = ((const float2*)(g_r + (size_t)v * 64))[lane];
    float2 o;
    o.x = fmaf(ax, rc, rr.x);
    o.y = fmaf(ay, rc, rr.y);
    ((float2*)(g_h2 + (size_t)v * 64))[lane] = o;
}

// ---------------- GCN propagation: warp per node, 64 features -------------------
__global__ void iconv_kernel(float* __restrict__ out) {
    int v = blockIdx.x * (blockDim.x >> 5) + (threadIdx.x >> 5);
    if (v >= NN) return;
    const float* h2 = (const float*)g_h2;
    int lane = threadIdx.x & 31;
    float dv = g_dis[v];
    float2 hv = ((const float2*)(h2 + (size_t)v * 64))[lane];
    float accx = dv * hv.x, accy = dv * hv.y;   // self loop (outer dv at end)
    int beg = g_off[v], end = g_off[v + 1];
    int j = beg;
    for (; j + 3 < end; j += 4) {
        int s0 = g_csrc[j], s1 = g_csrc[j + 1], s2 = g_csrc[j + 2], s3 = g_csrc[j + 3];
        float d0 = g_dis[s0], d1 = g_dis[s1], d2 = g_dis[s2], d3 = g_dis[s3];
        float2 t0 = ((const float2*)(h2 + (size_t)s0 * 64))[lane];
        float2 t1 = ((const float2*)(h2 + (size_t)s1 * 64))[lane];
        float2 t2 = ((const float2*)(h2 + (size_t)s2 * 64))[lane];
        float2 t3 = ((const float2*)(h2 + (size_t)s3 * 64))[lane];
        accx += (d0 * t0.x + d1 * t1.x) + (d2 * t2.x + d3 * t3.x);
        accy += (d0 * t0.y + d1 * t1.y) + (d2 * t2.y + d3 * t3.y);
    }
    for (; j < end; j++) {
        int s = g_csrc[j];
        float ds = g_dis[s];
        float2 t = ((const float2*)(h2 + (size_t)s * 64))[lane];
        accx += ds * t.x; accy += ds * t.y;
    }
    float2 r;
    r.x = dv * accx;
    r.y = dv * accy;
    ((float2*)(out + (size_t)v * 64))[lane] = r;
}

// ---------------- launcher (kernel launches ONLY) --------------------------------
extern "C" void kernel_launch(void* const* d_in, const int* in_sizes, int n_in,
                              void* d_out, int out_size) {
    const float* x   = (const float*)d_in[0];
    const int*   ei  = (const int*)d_in[1];   // int32 (JAX x64 disabled)
    const float* W1l = (const float*)d_in[2];
    const float* b1  = (const float*)d_in[3];
    const float* W1r = (const float*)d_in[4];
    const float* W2l = (const float*)d_in[5];
    const float* b2  = (const float*)d_in[6];
    const float* W2r = (const float*)d_in[7];
    float* out = (float*)d_out;

    const int* src = ei;
    const int* dst = ei + EE;

    const int EB = (EE + 255) / 256;
    const int NB = (NN + 255) / 256;

    zero_counts_kernel<<<NB, 256>>>();
    count_deg_kernel<<<(EE / 4 + 255) / 256, 256>>>((const int4*)dst);
    scan_deg_kernel<<<1, 1024>>>();
    build_csr_kernel<<<EB, 256>>>(src, dst);
    prep_kernel<<<NB, 256>>>();

    const int WARP_GRID = (NN + 7) / 8;   // 8 warps (nodes) per 256-thread block

    // layer 1: P = x@W1l^T, R = x@W1r^T + b1;  h = relu(rcnt*AggSum(P) + R)
    gemm_dual<1, 128, 64><<<(NN + 63) / 64, 256>>>(x, W1l, W1r, b1);
    agg128_relu_kernel<<<WARP_GRID, 256>>>();

    // layer 2: P2 = h@W2l^T, R2 = h@W2r^T + b2;  h2 = rcnt*AggSum(P2) + R2
    gemm_dual<2, 64, 128><<<(NN + 127) / 128, 256>>>(x, W2l, W2r, b2);
    agg64_kernel<<<WARP_GRID, 256>>>();

    // iconv: out = D^-1/2 (A+I) D^-1/2 h2
    iconv_kernel<<<WARP_GRID, 256>>>(out);
}

// round 5
// speedup vs baseline: 1.2342x; 1.0031x over previous
#include <cuda_runtime.h>
#include <cstdint>

#define NN 100000
#define EE 1600000
#define KF 128

// ---------------- scratch (static device globals; no runtime alloc) ----------
__device__ __align__(16) float g_p[(size_t)NN * 128];   // X @ Wl^T   (layer1: stride 128, layer2: stride 64)
__device__ __align__(16) float g_r[(size_t)NN * 128];   // X @ Wr^T+b (same packing)
__device__ __align__(16) float g_h[(size_t)NN * 128];   // layer-1 output
__device__ __align__(16) float g_h2[(size_t)NN * 64];   // layer-2 output
__device__ int   g_deg[NN];
__device__ int   g_fill[NN];
__device__ int   g_off[NN + 1];
__device__ int   g_csrc[EE];
__device__ float g_rcnt[NN];       // 1/max(deg,1)
__device__ float g_dis[NN];        // rsqrt(deg+1)

// ---------------- packed fp32x2 helpers (sm_103a) ------------------------------
__device__ __forceinline__ unsigned long long pk2(float lo, float hi) {
    unsigned long long r;
    asm("mov.b64 %0, {%1, %2};" : "=l"(r) : "f"(lo), "f"(hi));
    return r;
}
__device__ __forceinline__ void upk2(float& lo, float& hi, unsigned long long v) {
    asm("mov.b64 {%0, %1}, %2;" : "=f"(lo), "=f"(hi) : "l"(v));
}
__device__ __forceinline__ void ffma2(unsigned long long& d, unsigned long long a,
                                      unsigned long long b) {
    asm("fma.rn.f32x2 %0, %1, %2, %0;" : "+l"(d) : "l"(a), "l"(b));
}

// ---------------- init + CSR build ---------------------------------------------
__global__ void zero_counts_kernel() {
    int v = blockIdx.x * blockDim.x + threadIdx.x;
    if (v < NN) { g_deg[v] = 0; g_fill[v] = 0; }
}

__global__ void count_deg_kernel(const int4* __restrict__ dst4) {
    int e = blockIdx.x * blockDim.x + threadIdx.x;
    if (e < EE / 4) {
        int4 d = dst4[e];
        if ((unsigned)d.x < NN) atomicAdd(&g_deg[d.x], 1);
        if ((unsigned)d.y < NN) atomicAdd(&g_deg[d.y], 1);
        if ((unsigned)d.z < NN) atomicAdd(&g_deg[d.z], 1);
        if ((unsigned)d.w < NN) atomicAdd(&g_deg[d.w], 1);
    }
}

// single-block exclusive scan over g_deg -> g_off
__global__ void scan_deg_kernel() {
    __shared__ int warp_sums[32];
    __shared__ int carry;
    const int tid = threadIdx.x, lane = tid & 31, wid = tid >> 5;
    if (tid == 0) carry = 0;
    __syncthreads();
    for (int base = 0; base < NN; base += 1024) {
        int i = base + tid;
        int v = (i < NN) ? g_deg[i] : 0;
        int inc = v;
        #pragma unroll
        for (int o = 1; o < 32; o <<= 1) {
            int t = __shfl_up_sync(0xffffffffu, inc, o);
            if (lane >= o) inc += t;
        }
        if (lane == 31) warp_sums[wid] = inc;
        __syncthreads();
        if (wid == 0) {
            int s = warp_sums[lane];
            #pragma unroll
            for (int o = 1; o < 32; o <<= 1) {
                int t = __shfl_up_sync(0xffffffffu, s, o);
                if (lane >= o) s += t;
            }
            warp_sums[lane] = s;
        }
        __syncthreads();
        int warp_off = (wid > 0) ? warp_sums[wid - 1] : 0;
        if (i < NN) g_off[i] = carry + warp_off + (inc - v);
        int total = warp_sums[31];
        __syncthreads();
        if (tid == 0) carry += total;
        __syncthreads();
    }
    if (threadIdx.x == 0) g_off[NN] = carry;
}

__global__ void build_csr_kernel(const int* __restrict__ src,
                                 const int* __restrict__ dst) {
    int e = blockIdx.x * blockDim.x + threadIdx.x;
    if (e >= EE) return;
    unsigned d = (unsigned)dst[e];
    unsigned s = (unsigned)src[e];
    if (d >= NN || s >= NN) return;
    int p = g_off[d] + atomicAdd(&g_fill[d], 1);
    g_csrc[p] = (int)s;
}

__global__ void prep_kernel() {
    int v = blockIdx.x * blockDim.x + threadIdx.x;
    if (v >= NN) return;
    float d = (float)g_deg[v];
    g_rcnt[v] = 1.0f / fmaxf(d, 1.0f);
    g_dis[v]  = rsqrtf(d + 1.0f);
}

// ---------------- dual GEMM: P = X@Wl^T, R = X@Wr^T + b  (f32x2 packed FMA) ----
template <int LAYER, int BNH, int BM>
__global__ void __launch_bounds__(256)
gemm_dual(const float* __restrict__ xin,
          const float* __restrict__ Wl, const float* __restrict__ Wr,
          const float* __restrict__ bias) {
    constexpr int K = KF;
    constexpr int BK = 16;
    constexpr int N2 = 2 * BNH;
    constexpr int TN = 8;
    constexpr int THR_C = N2 / TN;
    constexpr int THR_R = 256 / THR_C;
    constexpr int TM = BM / THR_R;     // == 8
    constexpr int LDA = BM + 4;
    constexpr int LDW = N2 + 4;
    __shared__ float sX[BK][LDA];
    __shared__ float sW[BK][LDW];

    const float* X = (LAYER == 1) ? xin : (const float*)g_h;
    float* P = (float*)g_p;
    float* R = (float*)g_r;

    const int tid = threadIdx.x;
    const int row0 = blockIdx.x * BM;
    const int tc = tid % THR_C;
    const int tr = tid / THR_C;
    const int r0 = tr * TM;
    const int c0 = tc * TN;

    unsigned long long acc[TM][TN / 2];
    #pragma unroll
    for (int i = 0; i < TM; i++)
        #pragma unroll
        for (int j = 0; j < TN / 2; j++) acc[i][j] = 0ull;

    for (int k0 = 0; k0 < K; k0 += BK) {
        #pragma unroll
        for (int i = tid; i < BM * BK; i += 256) {
            int m = i >> 4, k = i & 15;
            int gr = row0 + m;
            sX[k][m] = (gr < NN) ? X[(size_t)gr * K + k0 + k] : 0.f;
        }
        #pragma unroll
        for (int i = tid; i < N2 * BK; i += 256) {
            int c = i >> 4, k = i & 15;
            sW[k][c] = (c < BNH) ? Wl[(size_t)c * K + k0 + k]
                                 : Wr[(size_t)(c - BNH) * K + k0 + k];
        }
        __syncthreads();
        #pragma unroll
        for (int k = 0; k < BK; k++) {
            float af[TM];
            #pragma unroll
            for (int i = 0; i < TM; i += 4)
                *(float4*)&af[i] = *(const float4*)&sX[k][r0 + i];
            ulonglong2 w01 = *(const ulonglong2*)&sW[k][c0];
            ulonglong2 w23 = *(const ulonglong2*)&sW[k][c0 + 4];
            unsigned long long wq[4] = {w01.x, w01.y, w23.x, w23.y};
            #pragma unroll
            for (int i = 0; i < TM; i++) {
                unsigned long long ap = pk2(af[i], af[i]);
                #pragma unroll
                for (int j = 0; j < TN / 2; j++) ffma2(acc[i][j], ap, wq[j]);
            }
        }
        __syncthreads();
    }

    const bool isP = (c0 < BNH);
    const int  cc  = isP ? c0 : (c0 - BNH);
    float* dstb = isP ? P : R;
    float bj[TN];
    #pragma unroll
    for (int j = 0; j < TN; j++) bj[j] = isP ? 0.f : bias[cc + j];

    #pragma unroll
    for (int i = 0; i < TM; i++) {
        int gr = row0 + r0 + i;
        if (gr >= NN) continue;
        float o[TN];
        #pragma unroll
        for (int j = 0; j < TN / 2; j++) {
            float lo, hi;
            upk2(lo, hi, acc[i][j]);
            o[2 * j]     = lo + bj[2 * j];
            o[2 * j + 1] = hi + bj[2 * j + 1];
        }
        *(float4*)&dstb[(size_t)gr * BNH + cc]     = *(float4*)&o[0];
        *(float4*)&dstb[(size_t)gr * BNH + cc + 4] = *(float4*)&o[4];
    }
}

// ---------------- fused aggregation epilogues -----------------------------------
__global__ void agg128_relu_kernel() {
    int v = blockIdx.x * (blockDim.x >> 5) + (threadIdx.x >> 5);
    if (v >= NN) return;
    int lane = threadIdx.x & 31;
    const float* P = (const float*)g_p;
    int beg = g_off[v], end = g_off[v + 1];
    float4 acc = make_float4(0.f, 0.f, 0.f, 0.f);
    int j = beg;
    for (; j + 3 < end; j += 4) {
        int s0 = g_csrc[j], s1 = g_csrc[j + 1], s2 = g_csrc[j + 2], s3 = g_csrc[j + 3];
        float4 t0 = ((const float4*)(P + (size_t)s0 * 128))[lane];
        float4 t1 = ((const float4*)(P + (size_t)s1 * 128))[lane];
        float4 t2 = ((const float4*)(P + (size_t)s2 * 128))[lane];
        float4 t3 = ((const float4*)(P + (size_t)s3 * 128))[lane];
        acc.x += (t0.x + t1.x) + (t2.x + t3.x);
        acc.y += (t0.y + t1.y) + (t2.y + t3.y);
        acc.z += (t0.z + t1.z) + (t2.z + t3.z);
        acc.w += (t0.w + t1.w) + (t2.w + t3.w);
    }
    for (; j < end; j++) {
        int s = g_csrc[j];
        float4 t = ((const float4*)(P + (size_t)s * 128))[lane];
        acc.x += t.x; acc.y += t.y; acc.z += t.z; acc.w += t.w;
    }
    float rc = g_rcnt[v];
    float4 rr = ((const float4*)(g_r + (size_t)v * 128))[lane];
    float4 o;
    o.x = fmaxf(fmaf(acc.x, rc, rr.x), 0.f);
    o.y = fmaxf(fmaf(acc.y, rc, rr.y), 0.f);
    o.z = fmaxf(fmaf(acc.z, rc, rr.z), 0.f);
    o.w = fmaxf(fmaf(acc.w, rc, rr.w), 0.f);
    ((float4*)(g_h + (size_t)v * 128))[lane] = o;
}

__global__ void agg64_kernel() {
    int v = blockIdx.x * (blockDim.x >> 5) + (threadIdx.x >> 5);
    if (v >= NN) return;
    int lane = threadIdx.x & 31;
    const float* P = (const float*)g_p;   // packed stride 64
    int beg = g_off[v], end = g_off[v + 1];
    float ax = 0.f, ay = 0.f;
    int j = beg;
    for (; j + 3 < end; j += 4) {
        int s0 = g_csrc[j], s1 = g_csrc[j + 1], s2 = g_csrc[j + 2], s3 = g_csrc[j + 3];
        float2 t0 = ((const float2*)(P + (size_t)s0 * 64))[lane];
        float2 t1 = ((const float2*)(P + (size_t)s1 * 64))[lane];
        float2 t2 = ((const float2*)(P + (size_t)s2 * 64))[lane];
        float2 t3 = ((const float2*)(P + (size_t)s3 * 64))[lane];
        ax += (t0.x + t1.x) + (t2.x + t3.x);
        ay += (t0.y + t1.y) + (t2.y + t3.y);
    }
    for (; j < end; j++) {
        int s = g_csrc[j];
        float2 t = ((const float2*)(P + (size_t)s * 64))[lane];
        ax += t.x; ay += t.y;
    }
    float rc = g_rcnt[v];
    float2 rr = ((const float2*)(g_r + (size_t)v * 64))[lane];
    float2 o;
    o.x = fmaf(ax, rc, rr.x);
    o.y = fmaf(ay, rc, rr.y);
    ((float2*)(g_h2 + (size_t)v * 64))[lane] = o;
}

// ---------------- GCN propagation -----------------------------------------------
__global__ void iconv_kernel(float* __restrict__ out) {
    int v = blockIdx.x * (blockDim.x >> 5) + (threadIdx.x >> 5);
    if (v >= NN) return;
    const float* h2 = (const float*)g_h2;
    int lane = threadIdx.x & 31;
    float dv = g_dis[v];
    float2 hv = ((const float2*)(h2 + (size_t)v * 64))[lane];
    float accx = dv * hv.x, accy = dv * hv.y;
    int beg = g_off[v], end = g_off[v + 1];
    int j = beg;
    for (; j + 3 < end; j += 4) {
        int s0 = g_csrc[j], s1 = g_csrc[j + 1], s2 = g_csrc[j + 2], s3 = g_csrc[j + 3];
        float d0 = g_dis[s0], d1 = g_dis[s1], d2 = g_dis[s2], d3 = g_dis[s3];
        float2 t0 = ((const float2*)(h2 + (size_t)s0 * 64))[lane];
        float2 t1 = ((const float2*)(h2 + (size_t)s1 * 64))[lane];
        float2 t2 = ((const float2*)(h2 + (size_t)s2 * 64))[lane];
        float2 t3 = ((const float2*)(h2 + (size_t)s3 * 64))[lane];
        accx += (d0 * t0.x + d1 * t1.x) + (d2 * t2.x + d3 * t3.x);
        accy += (d0 * t0.y + d1 * t1.y) + (d2 * t2.y + d3 * t3.y);
    }
    for (; j < end; j++) {
        int s = g_csrc[j];
        float ds = g_dis[s];
        float2 t = ((const float2*)(h2 + (size_t)s * 64))[lane];
        accx += ds * t.x; accy += ds * t.y;
    }
    float2 r;
    r.x = dv * accx;
    r.y = dv * accy;
    ((float2*)(out + (size_t)v * 64))[lane] = r;
}

// ---------------- launcher: parallel CSR / GEMM1 branches via stream fork -------
extern "C" void kernel_launch(void* const* d_in, const int* in_sizes, int n_in,
                              void* d_out, int out_size) {
    const float* x   = (const float*)d_in[0];
    const int*   ei  = (const int*)d_in[1];   // int32 (JAX x64 disabled)
    const float* W1l = (const float*)d_in[2];
    const float* b1  = (const float*)d_in[3];
    const float* W1r = (const float*)d_in[4];
    const float* W2l = (const float*)d_in[5];
    const float* b2  = (const float*)d_in[6];
    const float* W2r = (const float*)d_in[7];
    float* out = (float*)d_out;

    const int* src = ei;
    const int* dst = ei + EE;

    // one-time side-stream/event init (resource setup only; identical work per call)
    static cudaStream_t s_gemm = nullptr;
    static cudaEvent_t  ev_fork = nullptr, ev_join = nullptr;
    static bool tried = false;
    if (!tried) {
        tried = true;
        if (cudaStreamCreateWithFlags(&s_gemm, cudaStreamNonBlocking) != cudaSuccess)
            s_gemm = nullptr;
        if (s_gemm) {
            if (cudaEventCreateWithFlags(&ev_fork, cudaEventDisableTiming) != cudaSuccess ||
                cudaEventCreateWithFlags(&ev_join, cudaEventDisableTiming) != cudaSuccess) {
                s_gemm = nullptr;
            }
        }
    }

    const int EB = (EE + 255) / 256;
    const int NB = (NN + 255) / 256;
    const int WARP_GRID = (NN + 7) / 8;
    const int G1_GRID = (NN + 63) / 64;
    const int G2_GRID = (NN + 127) / 128;

    if (s_gemm) {
        // fork: GEMM1 runs concurrently with the CSR build chain
        cudaEventRecord(ev_fork, 0);
        cudaStreamWaitEvent(s_gemm, ev_fork, 0);
        gemm_dual<1, 128, 64><<<G1_GRID, 256, 0, s_gemm>>>(x, W1l, W1r, b1);
        cudaEventRecord(ev_join, s_gemm);

        zero_counts_kernel<<<NB, 256>>>();
        count_deg_kernel<<<(EE / 4 + 255) / 256, 256>>>((const int4*)dst);
        scan_deg_kernel<<<1, 1024>>>();
        build_csr_kernel<<<EB, 256>>>(src, dst);
        prep_kernel<<<NB, 256>>>();

        cudaStreamWaitEvent(0, ev_join, 0);   // join before consuming g_p/g_r
    } else {
        // fallback: fully sequential
        zero_counts_kernel<<<NB, 256>>>();
        count_deg_kernel<<<(EE / 4 + 255) / 256, 256>>>((const int4*)dst);
        scan_deg_kernel<<<1, 1024>>>();
        build_csr_kernel<<<EB, 256>>>(src, dst);
        prep_kernel<<<NB, 256>>>();
        gemm_dual<1, 128, 64><<<G1_GRID, 256>>>(x, W1l, W1r, b1);
    }

    // layer 1 epilogue: h = relu(rcnt*AggSum(P) + R)
    agg128_relu_kernel<<<WARP_GRID, 256>>>();

    // layer 2: P2 = h@W2l^T, R2 = h@W2r^T + b2;  h2 = rcnt*AggSum(P2) + R2
    gemm_dual<2, 64, 128><<<G2_GRID, 256>>>(x, W2l, W2r, b2);
    agg64_kernel<<<WARP_GRID, 256>>>();

    // iconv: out = D^-1/2 (A+I) D^-1/2 h2
    iconv_kernel<<<WARP_GRID, 256>>>(out);
}

// round 6
// speedup vs baseline: 1.4448x; 1.1706x over previous
#include <cuda_runtime.h>
#include <cstdint>

#define NN 100000
#define EE 1600000
#define KF 128
#define SCAN_BLK 98           // ceil(100000/1024)

// ---------------- scratch (static device globals; no runtime alloc) ----------
__device__ __align__(16) float g_p[(size_t)NN * 128];   // X @ Wl^T
__device__ __align__(16) float g_r[(size_t)NN * 128];   // X @ Wr^T + b
__device__ __align__(16) float g_h[(size_t)NN * 128];   // layer-1 output
__device__ __align__(16) float g_h2[(size_t)NN * 64];   // layer-2 output
__device__ int   g_deg[NN];
__device__ int   g_fill[NN];
__device__ int   g_off[NN + 1];
__device__ int   g_bsum[SCAN_BLK];   // per-block totals
__device__ int   g_boff[SCAN_BLK];   // per-block exclusive offsets
__device__ int   g_csrc[EE];
__device__ float g_rcnt[NN];
__device__ float g_dis[NN];

// ---------------- packed fp32x2 helpers (sm_103a) ------------------------------
__device__ __forceinline__ unsigned long long pk2(float lo, float hi) {
    unsigned long long r;
    asm("mov.b64 %0, {%1, %2};" : "=l"(r) : "f"(lo), "f"(hi));
    return r;
}
__device__ __forceinline__ void upk2(float& lo, float& hi, unsigned long long v) {
    asm("mov.b64 {%0, %1}, %2;" : "=f"(lo), "=f"(hi) : "l"(v));
}
__device__ __forceinline__ void ffma2(unsigned long long& d, unsigned long long a,
                                      unsigned long long b) {
    asm("fma.rn.f32x2 %0, %1, %2, %0;" : "+l"(d) : "l"(a), "l"(b));
}

// ---------------- init + CSR build ---------------------------------------------
__global__ void zero_counts_kernel() {
    int v = blockIdx.x * blockDim.x + threadIdx.x;
    if (v < NN) { g_deg[v] = 0; g_fill[v] = 0; }
}

__global__ void count_deg_kernel(const int4* __restrict__ dst4) {
    int e = blockIdx.x * blockDim.x + threadIdx.x;
    if (e < EE / 4) {
        int4 d = dst4[e];
        if ((unsigned)d.x < NN) atomicAdd(&g_deg[d.x], 1);
        if ((unsigned)d.y < NN) atomicAdd(&g_deg[d.y], 1);
        if ((unsigned)d.z < NN) atomicAdd(&g_deg[d.z], 1);
        if ((unsigned)d.w < NN) atomicAdd(&g_deg[d.w], 1);
    }
}

// ---- scan pass A: per-block (1024 elems) local exclusive scan + block total ----
__global__ void scanA_kernel() {
    __shared__ int warp_sums[32];
    const int tid = threadIdx.x, lane = tid & 31, wid = tid >> 5;
    int i = blockIdx.x * 1024 + tid;
    int v = (i < NN) ? g_deg[i] : 0;
    int inc = v;
    #pragma unroll
    for (int o = 1; o < 32; o <<= 1) {
        int t = __shfl_up_sync(0xffffffffu, inc, o);
        if (lane >= o) inc += t;
    }
    if (lane == 31) warp_sums[wid] = inc;
    __syncthreads();
    if (wid == 0) {
        int s = warp_sums[lane];
        #pragma unroll
        for (int o = 1; o < 32; o <<= 1) {
            int t = __shfl_up_sync(0xffffffffu, s, o);
            if (lane >= o) s += t;
        }
        warp_sums[lane] = s;
    }
    __syncthreads();
    int warp_off = (wid > 0) ? warp_sums[wid - 1] : 0;
    if (i < NN) g_off[i] = warp_off + (inc - v);     // block-local exclusive
    if (tid == 1023) g_bsum[blockIdx.x] = warp_sums[31];
}

// ---- scan pass B: 1 block scans the 98 block totals ----------------------------
__global__ void scanB_kernel() {
    __shared__ int warp_sums[4];
    const int tid = threadIdx.x, lane = tid & 31, wid = tid >> 5;  // 128 threads
    int v = (tid < SCAN_BLK) ? g_bsum[tid] : 0;
    int inc = v;
    #pragma unroll
    for (int o = 1; o < 32; o <<= 1) {
        int t = __shfl_up_sync(0xffffffffu, inc, o);
        if (lane >= o) inc += t;
    }
    if (lane == 31) warp_sums[wid] = inc;
    __syncthreads();
    int carry = 0;
    #pragma unroll
    for (int w = 0; w < 4; w++) {
        if (w == wid) break;
        carry += warp_sums[w];
    }
    if (tid < SCAN_BLK) g_boff[tid] = carry + inc - v;
    if (tid == 127) {
        int total = 0;
        #pragma unroll
        for (int w = 0; w < 4; w++) total += warp_sums[w];
        g_off[NN] = total;
    }
}

// ---- scan pass C: add block offsets; fused prep (rcnt/dis) ---------------------
__global__ void scanC_kernel() {
    int i = blockIdx.x * blockDim.x + threadIdx.x;
    if (i >= NN) return;
    g_off[i] += g_boff[i >> 10];
    float d = (float)g_deg[i];
    g_rcnt[i] = 1.0f / fmaxf(d, 1.0f);
    g_dis[i]  = rsqrtf(d + 1.0f);
}

__global__ void build_csr_kernel(const int* __restrict__ src,
                                 const int* __restrict__ dst) {
    int e = blockIdx.x * blockDim.x + threadIdx.x;
    if (e >= EE) return;
    unsigned d = (unsigned)dst[e];
    unsigned s = (unsigned)src[e];
    if (d >= NN || s >= NN) return;
    int p = g_off[d] + atomicAdd(&g_fill[d], 1);
    g_csrc[p] = (int)s;
}

// ---------------- dual GEMM: P = X@Wl^T, R = X@Wr^T + b  (f32x2 packed FMA) ----
template <int LAYER, int BNH, int BM>
__global__ void __launch_bounds__(256)
gemm_dual(const float* __restrict__ xin,
          const float* __restrict__ Wl, const float* __restrict__ Wr,
          const float* __restrict__ bias) {
    constexpr int K = KF;
    constexpr int BK = 16;
    constexpr int N2 = 2 * BNH;
    constexpr int TN = 8;
    constexpr int THR_C = N2 / TN;
    constexpr int THR_R = 256 / THR_C;
    constexpr int TM = BM / THR_R;
    constexpr int LDA = BM + 4;
    constexpr int LDW = N2 + 4;
    __shared__ float sX[BK][LDA];
    __shared__ float sW[BK][LDW];

    const float* X = (LAYER == 1) ? xin : (const float*)g_h;
    float* P = (float*)g_p;
    float* R = (float*)g_r;

    const int tid = threadIdx.x;
    const int row0 = blockIdx.x * BM;
    const int tc = tid % THR_C;
    const int tr = tid / THR_C;
    const int r0 = tr * TM;
    const int c0 = tc * TN;

    unsigned long long acc[TM][TN / 2];
    #pragma unroll
    for (int i = 0; i < TM; i++)
        #pragma unroll
        for (int j = 0; j < TN / 2; j++) acc[i][j] = 0ull;

    for (int k0 = 0; k0 < K; k0 += BK) {
        #pragma unroll
        for (int i = tid; i < BM * BK; i += 256) {
            int m = i >> 4, k = i & 15;
            int gr = row0 + m;
            sX[k][m] = (gr < NN) ? X[(size_t)gr * K + k0 + k] : 0.f;
        }
        #pragma unroll
        for (int i = tid; i < N2 * BK; i += 256) {
            int c = i >> 4, k = i & 15;
            sW[k][c] = (c < BNH) ? Wl[(size_t)c * K + k0 + k]
                                 : Wr[(size_t)(c - BNH) * K + k0 + k];
        }
        __syncthreads();
        #pragma unroll
        for (int k = 0; k < BK; k++) {
            float af[TM];
            #pragma unroll
            for (int i = 0; i < TM; i += 4)
                *(float4*)&af[i] = *(const float4*)&sX[k][r0 + i];
            ulonglong2 w01 = *(const ulonglong2*)&sW[k][c0];
            ulonglong2 w23 = *(const ulonglong2*)&sW[k][c0 + 4];
            unsigned long long wq[4] = {w01.x, w01.y, w23.x, w23.y};
            #pragma unroll
            for (int i = 0; i < TM; i++) {
                unsigned long long ap = pk2(af[i], af[i]);
                #pragma unroll
                for (int j = 0; j < TN / 2; j++) ffma2(acc[i][j], ap, wq[j]);
            }
        }
        __syncthreads();
    }

    const bool isP = (c0 < BNH);
    const int  cc  = isP ? c0 : (c0 - BNH);
    float* dstb = isP ? P : R;
    float bj[TN];
    #pragma unroll
    for (int j = 0; j < TN; j++) bj[j] = isP ? 0.f : bias[cc + j];

    #pragma unroll
    for (int i = 0; i < TM; i++) {
        int gr = row0 + r0 + i;
        if (gr >= NN) continue;
        float o[TN];
        #pragma unroll
        for (int j = 0; j < TN / 2; j++) {
            float lo, hi;
            upk2(lo, hi, acc[i][j]);
            o[2 * j]     = lo + bj[2 * j];
            o[2 * j + 1] = hi + bj[2 * j + 1];
        }
        *(float4*)&dstb[(size_t)gr * BNH + cc]     = *(float4*)&o[0];
        *(float4*)&dstb[(size_t)gr * BNH + cc + 4] = *(float4*)&o[4];
    }
}

// ---------------- fused aggregation epilogues -----------------------------------
__global__ void agg128_relu_kernel() {
    int v = blockIdx.x * (blockDim.x >> 5) + (threadIdx.x >> 5);
    if (v >= NN) return;
    int lane = threadIdx.x & 31;
    const float* P = (const float*)g_p;
    int beg = g_off[v], end = g_off[v + 1];
    float4 acc = make_float4(0.f, 0.f, 0.f, 0.f);
    int j = beg;
    for (; j + 3 < end; j += 4) {
        int s0 = g_csrc[j], s1 = g_csrc[j + 1], s2 = g_csrc[j + 2], s3 = g_csrc[j + 3];
        float4 t0 = ((const float4*)(P + (size_t)s0 * 128))[lane];
        float4 t1 = ((const float4*)(P + (size_t)s1 * 128))[lane];
        float4 t2 = ((const float4*)(P + (size_t)s2 * 128))[lane];
        float4 t3 = ((const float4*)(P + (size_t)s3 * 128))[lane];
        acc.x += (t0.x + t1.x) + (t2.x + t3.x);
        acc.y += (t0.y + t1.y) + (t2.y + t3.y);
        acc.z += (t0.z + t1.z) + (t2.z + t3.z);
        acc.w += (t0.w + t1.w) + (t2.w + t3.w);
    }
    for (; j < end; j++) {
        int s = g_csrc[j];
        float4 t = ((const float4*)(P + (size_t)s * 128))[lane];
        acc.x += t.x; acc.y += t.y; acc.z += t.z; acc.w += t.w;
    }
    float rc = g_rcnt[v];
    float4 rr = ((const float4*)(g_r + (size_t)v * 128))[lane];
    float4 o;
    o.x = fmaxf(fmaf(acc.x, rc, rr.x), 0.f);
    o.y = fmaxf(fmaf(acc.y, rc, rr.y), 0.f);
    o.z = fmaxf(fmaf(acc.z, rc, rr.z), 0.f);
    o.w = fmaxf(fmaf(acc.w, rc, rr.w), 0.f);
    ((float4*)(g_h + (size_t)v * 128))[lane] = o;
}

__global__ void agg64_kernel() {
    int v = blockIdx.x * (blockDim.x >> 5) + (threadIdx.x >> 5);
    if (v >= NN) return;
    int lane = threadIdx.x & 31;
    const float* P = (const float*)g_p;   // stride 64
    int beg = g_off[v], end = g_off[v + 1];
    float ax = 0.f, ay = 0.f;
    int j = beg;
    for (; j + 3 < end; j += 4) {
        int s0 = g_csrc[j], s1 = g_csrc[j + 1], s2 = g_csrc[j + 2], s3 = g_csrc[j + 3];
        float2 t0 = ((const float2*)(P + (size_t)s0 * 64))[lane];
        float2 t1 = ((const float2*)(P + (size_t)s1 * 64))[lane];
        float2 t2 = ((const float2*)(P + (size_t)s2 * 64))[lane];
        float2 t3 = ((const float2*)(P + (size_t)s3 * 64))[lane];
        ax += (t0.x + t1.x) + (t2.x + t3.x);
        ay += (t0.y + t1.y) + (t2.y + t3.y);
    }
    for (; j < end; j++) {
        int s = g_csrc[j];
        float2 t = ((const float2*)(P + (size_t)s * 64))[lane];
        ax += t.x; ay += t.y;
    }
    float rc = g_rcnt[v];
    float2 rr = ((const float2*)(g_r + (size_t)v * 64))[lane];
    float2 o;
    o.x = fmaf(ax, rc, rr.x);
    o.y = fmaf(ay, rc, rr.y);
    ((float2*)(g_h2 + (size_t)v * 64))[lane] = o;
}

// ---------------- GCN propagation -----------------------------------------------
__global__ void iconv_kernel(float* __restrict__ out) {
    int v = blockIdx.x * (blockDim.x >> 5) + (threadIdx.x >> 5);
    if (v >= NN) return;
    const float* h2 = (const float*)g_h2;
    int lane = threadIdx.x & 31;
    float dv = g_dis[v];
    float2 hv = ((const float2*)(h2 + (size_t)v * 64))[lane];
    float accx = dv * hv.x, accy = dv * hv.y;
    int beg = g_off[v], end = g_off[v + 1];
    int j = beg;
    for (; j + 3 < end; j += 4) {
        int s0 = g_csrc[j], s1 = g_csrc[j + 1], s2 = g_csrc[j + 2], s3 = g_csrc[j + 3];
        float d0 = g_dis[s0], d1 = g_dis[s1], d2 = g_dis[s2], d3 = g_dis[s3];
        float2 t0 = ((const float2*)(h2 + (size_t)s0 * 64))[lane];
        float2 t1 = ((const float2*)(h2 + (size_t)s1 * 64))[lane];
        float2 t2 = ((const float2*)(h2 + (size_t)s2 * 64))[lane];
        float2 t3 = ((const float2*)(h2 + (size_t)s3 * 64))[lane];
        accx += (d0 * t0.x + d1 * t1.x) + (d2 * t2.x + d3 * t3.x);
        accy += (d0 * t0.y + d1 * t1.y) + (d2 * t2.y + d3 * t3.y);
    }
    for (; j < end; j++) {
        int s = g_csrc[j];
        float ds = g_dis[s];
        float2 t = ((const float2*)(h2 + (size_t)s * 64))[lane];
        accx += ds * t.x; accy += ds * t.y;
    }
    float2 r;
    r.x = dv * accx;
    r.y = dv * accy;
    ((float2*)(out + (size_t)v * 64))[lane] = r;
}

// ---------------- launcher ------------------------------------------------------
extern "C" void kernel_launch(void* const* d_in, const int* in_sizes, int n_in,
                              void* d_out, int out_size) {
    const float* x   = (const float*)d_in[0];
    const int*   ei  = (const int*)d_in[1];   // int32 (JAX x64 disabled)
    const float* W1l = (const float*)d_in[2];
    const float* b1  = (const float*)d_in[3];
    const float* W1r = (const float*)d_in[4];
    const float* W2l = (const float*)d_in[5];
    const float* b2  = (const float*)d_in[6];
    const float* W2r = (const float*)d_in[7];
    float* out = (float*)d_out;

    const int* src = ei;
    const int* dst = ei + EE;

    static cudaStream_t s_gemm = nullptr;
    static cudaEvent_t  ev_fork = nullptr, ev_join = nullptr;
    static bool tried = false;
    if (!tried) {
        tried = true;
        if (cudaStreamCreateWithFlags(&s_gemm, cudaStreamNonBlocking) != cudaSuccess)
            s_gemm = nullptr;
        if (s_gemm) {
            if (cudaEventCreateWithFlags(&ev_fork, cudaEventDisableTiming) != cudaSuccess ||
                cudaEventCreateWithFlags(&ev_join, cudaEventDisableTiming) != cudaSuccess) {
                s_gemm = nullptr;
            }
        }
    }

    const int EB = (EE + 255) / 256;
    const int NB = (NN + 255) / 256;
    const int WARP_GRID = (NN + 7) / 8;
    const int G1_GRID = (NN + 63) / 64;
    const int G2_GRID = (NN + 127) / 128;

    if (s_gemm) {
        cudaEventRecord(ev_fork, 0);
        cudaStreamWaitEvent(s_gemm, ev_fork, 0);
        gemm_dual<1, 128, 64><<<G1_GRID, 256, 0, s_gemm>>>(x, W1l, W1r, b1);
        cudaEventRecord(ev_join, s_gemm);

        zero_counts_kernel<<<NB, 256>>>();
        count_deg_kernel<<<(EE / 4 + 255) / 256, 256>>>((const int4*)dst);
        scanA_kernel<<<SCAN_BLK, 1024>>>();
        scanB_kernel<<<1, 128>>>();
        scanC_kernel<<<NB, 256>>>();
        build_csr_kernel<<<EB, 256>>>(src, dst);

        cudaStreamWaitEvent(0, ev_join, 0);
    } else {
        zero_counts_kernel<<<NB, 256>>>();
        count_deg_kernel<<<(EE / 4 + 255) / 256, 256>>>((const int4*)dst);
        scanA_kernel<<<SCAN_BLK, 1024>>>();
        scanB_kernel<<<1, 128>>>();
        scanC_kernel<<<NB, 256>>>();
        build_csr_kernel<<<EB, 256>>>(src, dst);
        gemm_dual<1, 128, 64><<<G1_GRID, 256>>>(x, W1l, W1r, b1);
    }

    agg128_relu_kernel<<<WARP_GRID, 256>>>();

    gemm_dual<2, 64, 128><<<G2_GRID, 256>>>(x, W2l, W2r, b2);
    agg64_kernel<<<WARP_GRID, 256>>>();

    iconv_kernel<<<WARP_GRID, 256>>>(out);
}

// round 7
// speedup vs baseline: 1.7241x; 1.1933x over previous
#include <cuda_runtime.h>
#include <cstdint>

#define NN 100000
#define EE 1600000
#define KF 128
#define SCAN_BLK 98           // ceil(100000/1024)

// ---------------- scratch (static device globals; no runtime alloc) ----------
__device__ __align__(16) float g_p[(size_t)NN * 128];   // X @ Wl^T
__device__ __align__(16) float g_r[(size_t)NN * 128];   // X @ Wr^T + b
__device__ __align__(16) float g_h[(size_t)NN * 128];   // layer-1 output
__device__ __align__(16) float g_h2[(size_t)NN * 64];   // layer-2 output
__device__ int   g_deg[NN];
__device__ int   g_fill[NN];
__device__ int   g_off[NN + 1];
__device__ int   g_bsum[SCAN_BLK];
__device__ int   g_boff[SCAN_BLK];
__device__ int   g_csrc[EE];
__device__ float g_rcnt[NN];
__device__ float g_dis[NN];

// ---------------- init + CSR build ---------------------------------------------
__global__ void zero_counts_kernel() {
    int v = blockIdx.x * blockDim.x + threadIdx.x;
    if (v < NN) { g_deg[v] = 0; g_fill[v] = 0; }
}

__global__ void count_deg_kernel(const int4* __restrict__ dst4) {
    int e = blockIdx.x * blockDim.x + threadIdx.x;
    if (e < EE / 4) {
        int4 d = dst4[e];
        if ((unsigned)d.x < NN) atomicAdd(&g_deg[d.x], 1);
        if ((unsigned)d.y < NN) atomicAdd(&g_deg[d.y], 1);
        if ((unsigned)d.z < NN) atomicAdd(&g_deg[d.z], 1);
        if ((unsigned)d.w < NN) atomicAdd(&g_deg[d.w], 1);
    }
}

__global__ void scanA_kernel() {
    __shared__ int warp_sums[32];
    const int tid = threadIdx.x, lane = tid & 31, wid = tid >> 5;
    int i = blockIdx.x * 1024 + tid;
    int v = (i < NN) ? g_deg[i] : 0;
    int inc = v;
    #pragma unroll
    for (int o = 1; o < 32; o <<= 1) {
        int t = __shfl_up_sync(0xffffffffu, inc, o);
        if (lane >= o) inc += t;
    }
    if (lane == 31) warp_sums[wid] = inc;
    __syncthreads();
    if (wid == 0) {
        int s = warp_sums[lane];
        #pragma unroll
        for (int o = 1; o < 32; o <<= 1) {
            int t = __shfl_up_sync(0xffffffffu, s, o);
            if (lane >= o) s += t;
        }
        warp_sums[lane] = s;
    }
    __syncthreads();
    int warp_off = (wid > 0) ? warp_sums[wid - 1] : 0;
    if (i < NN) g_off[i] = warp_off + (inc - v);
    if (tid == 1023) g_bsum[blockIdx.x] = warp_sums[31];
}

__global__ void scanB_kernel() {
    __shared__ int warp_sums[4];
    const int tid = threadIdx.x, lane = tid & 31, wid = tid >> 5;  // 128 threads
    int v = (tid < SCAN_BLK) ? g_bsum[tid] : 0;
    int inc = v;
    #pragma unroll
    for (int o = 1; o < 32; o <<= 1) {
        int t = __shfl_up_sync(0xffffffffu, inc, o);
        if (lane >= o) inc += t;
    }
    if (lane == 31) warp_sums[wid] = inc;
    __syncthreads();
    int carry = 0;
    #pragma unroll
    for (int w = 0; w < 4; w++) {
        if (w == wid) break;
        carry += warp_sums[w];
    }
    if (tid < SCAN_BLK) g_boff[tid] = carry + inc - v;
    if (tid == 127) {
        int total = 0;
        #pragma unroll
        for (int w = 0; w < 4; w++) total += warp_sums[w];
        g_off[NN] = total;
    }
}

__global__ void scanC_kernel() {
    int i = blockIdx.x * blockDim.x + threadIdx.x;
    if (i >= NN) return;
    g_off[i] += g_boff[i >> 10];
    float d = (float)g_deg[i];
    g_rcnt[i] = 1.0f / fmaxf(d, 1.0f);
    g_dis[i]  = rsqrtf(d + 1.0f);
}

__global__ void build_csr_kernel(const int* __restrict__ src,
                                 const int* __restrict__ dst) {
    int e = blockIdx.x * blockDim.x + threadIdx.x;
    if (e >= EE) return;
    unsigned d = (unsigned)dst[e];
    unsigned s = (unsigned)src[e];
    if (d >= NN || s >= NN) return;
    int p = g_off[d] + atomicAdd(&g_fill[d], 1);
    g_csrc[p] = (int)s;
}

// ---------------- tf32 helpers ---------------------------------------------------
__device__ __forceinline__ void tf32split(float a, float& hi, float& lo) {
    uint32_t u;
    asm("cvt.rna.tf32.f32 %0, %1;" : "=r"(u) : "f"(a));
    hi = __uint_as_float(u);
    float r = a - hi;
    asm("cvt.rna.tf32.f32 %0, %1;" : "=r"(u) : "f"(r));
    lo = __uint_as_float(u);
}

__device__ __forceinline__ void mma_tf32(float* c, const uint32_t* a, const uint32_t* b) {
    asm volatile(
        "mma.sync.aligned.m16n8k8.row.col.f32.tf32.tf32.f32 "
        "{%0,%1,%2,%3}, {%4,%5,%6,%7}, {%8,%9}, {%0,%1,%2,%3};"
        : "+f"(c[0]), "+f"(c[1]), "+f"(c[2]), "+f"(c[3])
        : "r"(a[0]), "r"(a[1]), "r"(a[2]), "r"(a[3]), "r"(b[0]), "r"(b[1]));
}

// ---------------- tensor-core dual GEMM: [P | R] = X @ [Wl | Wr]^T (+b on R) ----
// 3-pass tf32 (hi*hi + hi*lo + lo*hi) — fp32-grade accuracy on the tensor pipe.
// Block tile 128(M) x 64(N) x 16(K); 8 warps as 4(M) x 2(N); warp tile 32x32.
template <int LAYER, int BNH>
__global__ void __launch_bounds__(256)
gemm_dual_tc(const float* __restrict__ xin,
             const float* __restrict__ Wl, const float* __restrict__ Wr,
             const float* __restrict__ bias) {
    constexpr int K = KF, BM = 128, BN = 64, BK = 16, LD = BK + 4;  // LD=20: conflict-free
    __shared__ float sAh[BM][LD], sAl[BM][LD];
    __shared__ float sBh[BN][LD], sBl[BN][LD];

    const float* X = (LAYER == 1) ? xin : (const float*)g_h;
    const int tid = threadIdx.x;
    const int lane = tid & 31, wid = tid >> 5;
    const int wm = wid & 3, wn = wid >> 2;      // 4 x 2 warp grid
    const int g = lane >> 2, t = lane & 3;
    const int row0 = blockIdx.x * BM;
    const int col0 = blockIdx.y * BN;           // within N2 = 2*BNH

    float acc[2][4][4];
    #pragma unroll
    for (int mf = 0; mf < 2; mf++)
        #pragma unroll
        for (int nf = 0; nf < 4; nf++)
            #pragma unroll
            for (int i = 0; i < 4; i++) acc[mf][nf][i] = 0.f;

    for (int k0 = 0; k0 < K; k0 += BK) {
        // A tile: 128x16 floats = 512 float4, 2 per thread
        #pragma unroll
        for (int i = 0; i < 2; i++) {
            int li = tid + i * 256;
            int r = li >> 2;
            int q = (li & 3) * 4;
            int gr = row0 + r;
            float4 v = (gr < NN) ? *(const float4*)&X[(size_t)gr * K + k0 + q]
                                 : make_float4(0.f, 0.f, 0.f, 0.f);
            float h0, l0, h1, l1, h2, l2, h3, l3;
            tf32split(v.x, h0, l0); tf32split(v.y, h1, l1);
            tf32split(v.z, h2, l2); tf32split(v.w, h3, l3);
            sAh[r][q] = h0; sAh[r][q + 1] = h1; sAh[r][q + 2] = h2; sAh[r][q + 3] = h3;
            sAl[r][q] = l0; sAl[r][q + 1] = l1; sAl[r][q + 2] = l2; sAl[r][q + 3] = l3;
        }
        // B tile: 64x16 floats = 256 float4, 1 per thread
        {
            int r = tid >> 2;
            int q = (tid & 3) * 4;
            int c = col0 + r;
            const float* Wsrc = (c < BNH) ? &Wl[(size_t)c * K] : &Wr[(size_t)(c - BNH) * K];
            float4 v = *(const float4*)&Wsrc[k0 + q];
            float h0, l0, h1, l1, h2, l2, h3, l3;
            tf32split(v.x, h0, l0); tf32split(v.y, h1, l1);
            tf32split(v.z, h2, l2); tf32split(v.w, h3, l3);
            sBh[r][q] = h0; sBh[r][q + 1] = h1; sBh[r][q + 2] = h2; sBh[r][q + 3] = h3;
            sBl[r][q] = l0; sBl[r][q + 1] = l1; sBl[r][q + 2] = l2; sBl[r][q + 3] = l3;
        }
        __syncthreads();

        #pragma unroll
        for (int kk = 0; kk < BK; kk += 8) {
            uint32_t ah[2][4], al[2][4], bh[4][2], bl[4][2];
            #pragma unroll
            for (int mf = 0; mf < 2; mf++) {
                int rb = wm * 32 + mf * 16;
                ah[mf][0] = __float_as_uint(sAh[rb + g][kk + t]);
                ah[mf][1] = __float_as_uint(sAh[rb + g + 8][kk + t]);
                ah[mf][2] = __float_as_uint(sAh[rb + g][kk + t + 4]);
                ah[mf][3] = __float_as_uint(sAh[rb + g + 8][kk + t + 4]);
                al[mf][0] = __float_as_uint(sAl[rb + g][kk + t]);
                al[mf][1] = __float_as_uint(sAl[rb + g + 8][kk + t]);
                al[mf][2] = __float_as_uint(sAl[rb + g][kk + t + 4]);
                al[mf][3] = __float_as_uint(sAl[rb + g + 8][kk + t + 4]);
            }
            #pragma unroll
            for (int nf = 0; nf < 4; nf++) {
                int nb = wn * 32 + nf * 8;
                bh[nf][0] = __float_as_uint(sBh[nb + g][kk + t]);
                bh[nf][1] = __float_as_uint(sBh[nb + g][kk + t + 4]);
                bl[nf][0] = __float_as_uint(sBl[nb + g][kk + t]);
                bl[nf][1] = __float_as_uint(sBl[nb + g][kk + t + 4]);
            }
            #pragma unroll
            for (int mf = 0; mf < 2; mf++)
                #pragma unroll
                for (int nf = 0; nf < 4; nf++) {
                    mma_tf32(acc[mf][nf], ah[mf], bh[nf]);   // hi*hi
                    mma_tf32(acc[mf][nf], ah[mf], bl[nf]);   // hi*lo
                    mma_tf32(acc[mf][nf], al[mf], bh[nf]);   // lo*hi
                }
        }
        __syncthreads();
    }

    // epilogue: whole block is either P or R (BN=64 divides BNH)
    const bool isP = (col0 < BNH);
    float* dstb = isP ? (float*)g_p : (float*)g_r;
    const int cb = col0 - (isP ? 0 : BNH);
    #pragma unroll
    for (int nf = 0; nf < 4; nf++) {
        int c = cb + wn * 32 + nf * 8 + 2 * t;
        float b0v = isP ? 0.f : bias[c];
        float b1v = isP ? 0.f : bias[c + 1];
        #pragma unroll
        for (int mf = 0; mf < 2; mf++) {
            int r = row0 + wm * 32 + mf * 16 + g;
            if (r < NN) {
                float2 o = make_float2(acc[mf][nf][0] + b0v, acc[mf][nf][1] + b1v);
                *(float2*)&dstb[(size_t)r * BNH + c] = o;
            }
            if (r + 8 < NN) {
                float2 o = make_float2(acc[mf][nf][2] + b0v, acc[mf][nf][3] + b1v);
                *(float2*)&dstb[(size_t)(r + 8) * BNH + c] = o;
            }
        }
    }
}

// ---------------- fused aggregation epilogues -----------------------------------
__global__ void agg128_relu_kernel() {
    int v = blockIdx.x * (blockDim.x >> 5) + (threadIdx.x >> 5);
    if (v >= NN) return;
    int lane = threadIdx.x & 31;
    const float* P = (const float*)g_p;
    int beg = g_off[v], end = g_off[v + 1];
    float4 acc = make_float4(0.f, 0.f, 0.f, 0.f);
    int j = beg;
    for (; j + 3 < end; j += 4) {
        int s0 = g_csrc[j], s1 = g_csrc[j + 1], s2 = g_csrc[j + 2], s3 = g_csrc[j + 3];
        float4 t0 = ((const float4*)(P + (size_t)s0 * 128))[lane];
        float4 t1 = ((const float4*)(P + (size_t)s1 * 128))[lane];
        float4 t2 = ((const float4*)(P + (size_t)s2 * 128))[lane];
        float4 t3 = ((const float4*)(P + (size_t)s3 * 128))[lane];
        acc.x += (t0.x + t1.x) + (t2.x + t3.x);
        acc.y += (t0.y + t1.y) + (t2.y + t3.y);
        acc.z += (t0.z + t1.z) + (t2.z + t3.z);
        acc.w += (t0.w + t1.w) + (t2.w + t3.w);
    }
    for (; j < end; j++) {
        int s = g_csrc[j];
        float4 t = ((const float4*)(P + (size_t)s * 128))[lane];
        acc.x += t.x; acc.y += t.y; acc.z += t.z; acc.w += t.w;
    }
    float rc = g_rcnt[v];
    float4 rr = ((const float4*)(g_r + (size_t)v * 128))[lane];
    float4 o;
    o.x = fmaxf(fmaf(acc.x, rc, rr.x), 0.f);
    o.y = fmaxf(fmaf(acc.y, rc, rr.y), 0.f);
    o.z = fmaxf(fmaf(acc.z, rc, rr.z), 0.f);
    o.w = fmaxf(fmaf(acc.w, rc, rr.w), 0.f);
    ((float4*)(g_h + (size_t)v * 128))[lane] = o;
}

__global__ void agg64_kernel() {
    int v = blockIdx.x * (blockDim.x >> 5) + (threadIdx.x >> 5);
    if (v >= NN) return;
    int lane = threadIdx.x & 31;
    const float* P = (const float*)g_p;   // stride 64
    int beg = g_off[v], end = g_off[v + 1];
    float ax = 0.f, ay = 0.f;
    int j = beg;
    for (; j + 3 < end; j += 4) {
        int s0 = g_csrc[j], s1 = g_csrc[j + 1], s2 = g_csrc[j + 2], s3 = g_csrc[j + 3];
        float2 t0 = ((const float2*)(P + (size_t)s0 * 64))[lane];
        float2 t1 = ((const float2*)(P + (size_t)s1 * 64))[lane];
        float2 t2 = ((const float2*)(P + (size_t)s2 * 64))[lane];
        float2 t3 = ((const float2*)(P + (size_t)s3 * 64))[lane];
        ax += (t0.x + t1.x) + (t2.x + t3.x);
        ay += (t0.y + t1.y) + (t2.y + t3.y);
    }
    for (; j < end; j++) {
        int s = g_csrc[j];
        float2 t = ((const float2*)(P + (size_t)s * 64))[lane];
        ax += t.x; ay += t.y;
    }
    float rc = g_rcnt[v];
    float2 rr = ((const float2*)(g_r + (size_t)v * 64))[lane];
    float2 o;
    o.x = fmaf(ax, rc, rr.x);
    o.y = fmaf(ay, rc, rr.y);
    ((float2*)(g_h2 + (size_t)v * 64))[lane] = o;
}

// ---------------- GCN propagation -----------------------------------------------
__global__ void iconv_kernel(float* __restrict__ out) {
    int v = blockIdx.x * (blockDim.x >> 5) + (threadIdx.x >> 5);
    if (v >= NN) return;
    const float* h2 = (const float*)g_h2;
    int lane = threadIdx.x & 31;
    float dv = g_dis[v];
    float2 hv = ((const float2*)(h2 + (size_t)v * 64))[lane];
    float accx = dv * hv.x, accy = dv * hv.y;
    int beg = g_off[v], end = g_off[v + 1];
    int j = beg;
    for (; j + 3 < end; j += 4) {
        int s0 = g_csrc[j], s1 = g_csrc[j + 1], s2 = g_csrc[j + 2], s3 = g_csrc[j + 3];
        float d0 = g_dis[s0], d1 = g_dis[s1], d2 = g_dis[s2], d3 = g_dis[s3];
        float2 t0 = ((const float2*)(h2 + (size_t)s0 * 64))[lane];
        float2 t1 = ((const float2*)(h2 + (size_t)s1 * 64))[lane];
        float2 t2 = ((const float2*)(h2 + (size_t)s2 * 64))[lane];
        float2 t3 = ((const float2*)(h2 + (size_t)s3 * 64))[lane];
        accx += (d0 * t0.x + d1 * t1.x) + (d2 * t2.x + d3 * t3.x);
        accy += (d0 * t0.y + d1 * t1.y) + (d2 * t2.y + d3 * t3.y);
    }
    for (; j < end; j++) {
        int s = g_csrc[j];
        float ds = g_dis[s];
        float2 t = ((const float2*)(h2 + (size_t)s * 64))[lane];
        accx += ds * t.x; accy += ds * t.y;
    }
    float2 r;
    r.x = dv * accx;
    r.y = dv * accy;
    ((float2*)(out + (size_t)v * 64))[lane] = r;
}

// ---------------- launcher ------------------------------------------------------
extern "C" void kernel_launch(void* const* d_in, const int* in_sizes, int n_in,
                              void* d_out, int out_size) {
    const float* x   = (const float*)d_in[0];
    const int*   ei  = (const int*)d_in[1];   // int32 (JAX x64 disabled)
    const float* W1l = (const float*)d_in[2];
    const float* b1  = (const float*)d_in[3];
    const float* W1r = (const float*)d_in[4];
    const float* W2l = (const float*)d_in[5];
    const float* b2  = (const float*)d_in[6];
    const float* W2r = (const float*)d_in[7];
    float* out = (float*)d_out;

    const int* src = ei;
    const int* dst = ei + EE;

    static cudaStream_t s_gemm = nullptr;
    static cudaEvent_t  ev_fork = nullptr, ev_join = nullptr;
    static bool tried = false;
    if (!tried) {
        tried = true;
        if (cudaStreamCreateWithFlags(&s_gemm, cudaStreamNonBlocking) != cudaSuccess)
            s_gemm = nullptr;
        if (s_gemm) {
            if (cudaEventCreateWithFlags(&ev_fork, cudaEventDisableTiming) != cudaSuccess ||
                cudaEventCreateWithFlags(&ev_join, cudaEventDisableTiming) != cudaSuccess) {
                s_gemm = nullptr;
            }
        }
    }

    const int EB = (EE + 255) / 256;
    const int NB = (NN + 255) / 256;
    const int WARP_GRID = (NN + 7) / 8;
    const dim3 G1((NN + 127) / 128, 4);   // N2 = 256
    const dim3 G2((NN + 127) / 128, 2);   // N2 = 128

    if (s_gemm) {
        cudaEventRecord(ev_fork, 0);
        cudaStreamWaitEvent(s_gemm, ev_fork, 0);
        gemm_dual_tc<1, 128><<<G1, 256, 0, s_gemm>>>(x, W1l, W1r, b1);
        cudaEventRecord(ev_join, s_gemm);

        zero_counts_kernel<<<NB, 256>>>();
        count_deg_kernel<<<(EE / 4 + 255) / 256, 256>>>((const int4*)dst);
        scanA_kernel<<<SCAN_BLK, 1024>>>();
        scanB_kernel<<<1, 128>>>();
        scanC_kernel<<<NB, 256>>>();
        build_csr_kernel<<<EB, 256>>>(src, dst);

        cudaStreamWaitEvent(0, ev_join, 0);
    } else {
        zero_counts_kernel<<<NB, 256>>>();
        count_deg_kernel<<<(EE / 4 + 255) / 256, 256>>>((const int4*)dst);
        scanA_kernel<<<SCAN_BLK, 1024>>>();
        scanB_kernel<<<1, 128>>>();
        scanC_kernel<<<NB, 256>>>();
        build_csr_kernel<<<EB, 256>>>(src, dst);
        gemm_dual_tc<1, 128><<<G1, 256>>>(x, W1l, W1r, b1);
    }

    agg128_relu_kernel<<<WARP_GRID, 256>>>();

    gemm_dual_tc<2, 64><<<G2, 256>>>(x, W2l, W2r, b2);
    agg64_kernel<<<WARP_GRID, 256>>>();

    iconv_kernel<<<WARP_GRID, 256>>>(out);
}

// round 8
// speedup vs baseline: 1.7443x; 1.0117x over previous
#include <cuda_runtime.h>
#include <cstdint>

#define NN 100000
#define EE 1600000
#define KF 128
#define SCAN_BLK 98           // ceil(100000/1024)

// ---------------- scratch (static device globals; no runtime alloc) ----------
__device__ __align__(16) float g_p[(size_t)NN * 128];   // X @ Wl^T
__device__ __align__(16) float g_r[(size_t)NN * 128];   // X @ Wr^T + b
__device__ __align__(16) float g_h[(size_t)NN * 128];   // layer-1 output
__device__ __align__(16) float g_h2[(size_t)NN * 64];   // dis-scaled layer-2 output
__device__ int   g_deg[NN];        // zeroed at END of each replay (and statically)
__device__ int   g_fill[NN];       // CSR write cursor (seeded = g_off in scanC)
__device__ int   g_off[NN + 1];
__device__ int   g_bsum[SCAN_BLK];
__device__ int   g_csrc[EE];
__device__ float g_rcnt[NN];
__device__ float g_dis[NN];

// ---------------- CSR build ------------------------------------------------------
__global__ void count_deg_kernel(const int4* __restrict__ dst4) {
    int e = blockIdx.x * blockDim.x + threadIdx.x;
    if (e < EE / 4) {
        int4 d = dst4[e];
        if ((unsigned)d.x < NN) atomicAdd(&g_deg[d.x], 1);
        if ((unsigned)d.y < NN) atomicAdd(&g_deg[d.y], 1);
        if ((unsigned)d.z < NN) atomicAdd(&g_deg[d.z], 1);
        if ((unsigned)d.w < NN) atomicAdd(&g_deg[d.w], 1);
    }
}

// pass A: per-1024-block local exclusive scan + block total
__global__ void scanA_kernel() {
    __shared__ int warp_sums[32];
    const int tid = threadIdx.x, lane = tid & 31, wid = tid >> 5;
    int i = blockIdx.x * 1024 + tid;
    int v = (i < NN) ? g_deg[i] : 0;
    int inc = v;
    #pragma unroll
    for (int o = 1; o < 32; o <<= 1) {
        int t = __shfl_up_sync(0xffffffffu, inc, o);
        if (lane >= o) inc += t;
    }
    if (lane == 31) warp_sums[wid] = inc;
    __syncthreads();
    if (wid == 0) {
        int s = warp_sums[lane];
        #pragma unroll
        for (int o = 1; o < 32; o <<= 1) {
            int t = __shfl_up_sync(0xffffffffu, s, o);
            if (lane >= o) s += t;
        }
        warp_sums[lane] = s;
    }
    __syncthreads();
    int warp_off = (wid > 0) ? warp_sums[wid - 1] : 0;
    if (i < NN) g_off[i] = warp_off + (inc - v);
    if (tid == 1023) g_bsum[blockIdx.x] = warp_sums[31];
}

// pass C (self-offsetting): add chunk offset, seed cursor, compute rcnt/dis.
// Each 256-thread block lies inside one 1024-chunk (256 | 1024).
__global__ void scanC_kernel() {
    __shared__ int s_off, s_tot;
    const int tid = threadIdx.x;
    const int chunk = blockIdx.x >> 2;
    if (tid < 32) {
        int p = 0, tot = 0;
        for (int j = tid; j < SCAN_BLK; j += 32) {
            int b = g_bsum[j];
            tot += b;
            if (j < chunk) p += b;
        }
        #pragma unroll
        for (int o = 16; o > 0; o >>= 1) {
            p   += __shfl_down_sync(0xffffffffu, p, o);
            tot += __shfl_down_sync(0xffffffffu, tot, o);
        }
        if (tid == 0) { s_off = p; s_tot = tot; }
    }
    __syncthreads();
    int i = blockIdx.x * 256 + tid;
    if (i < NN) {
        int off = g_off[i] + s_off;
        g_off[i]  = off;
        g_fill[i] = off;                      // seeded cursor for build
        float d = (float)g_deg[i];
        g_rcnt[i] = 1.0f / fmaxf(d, 1.0f);
        g_dis[i]  = rsqrtf(d + 1.0f);
    }
    if (blockIdx.x == gridDim.x - 1 && tid == 0) g_off[NN] = s_tot;
}

// single-atomic scatter, 4 edges per thread
__global__ void build_csr_kernel(const int4* __restrict__ src4,
                                 const int4* __restrict__ dst4) {
    int e = blockIdx.x * blockDim.x + threadIdx.x;
    if (e >= EE / 4) return;
    int4 d = dst4[e];
    int4 s = src4[e];
    if ((unsigned)d.x < NN && (unsigned)s.x < NN) g_csrc[atomicAdd(&g_fill[d.x], 1)] = s.x;
    if ((unsigned)d.y < NN && (unsigned)s.y < NN) g_csrc[atomicAdd(&g_fill[d.y], 1)] = s.y;
    if ((unsigned)d.z < NN && (unsigned)s.z < NN) g_csrc[atomicAdd(&g_fill[d.z], 1)] = s.z;
    if ((unsigned)d.w < NN && (unsigned)s.w < NN) g_csrc[atomicAdd(&g_fill[d.w], 1)] = s.w;
}

// zero g_deg for the NEXT replay (runs at graph end, overlapped on side stream)
__global__ void zero_deg_kernel() {
    int v = blockIdx.x * blockDim.x + threadIdx.x;
    if (v < NN) g_deg[v] = 0;
}

// ---------------- tf32 helpers ---------------------------------------------------
__device__ __forceinline__ void tf32split(float a, float& hi, float& lo) {
    uint32_t u;
    asm("cvt.rna.tf32.f32 %0, %1;" : "=r"(u) : "f"(a));
    hi = __uint_as_float(u);
    float r = a - hi;
    asm("cvt.rna.tf32.f32 %0, %1;" : "=r"(u) : "f"(r));
    lo = __uint_as_float(u);
}

__device__ __forceinline__ void mma_tf32(float* c, const uint32_t* a, const uint32_t* b) {
    asm volatile(
        "mma.sync.aligned.m16n8k8.row.col.f32.tf32.tf32.f32 "
        "{%0,%1,%2,%3}, {%4,%5,%6,%7}, {%8,%9}, {%0,%1,%2,%3};"
        : "+f"(c[0]), "+f"(c[1]), "+f"(c[2]), "+f"(c[3])
        : "r"(a[0]), "r"(a[1]), "r"(a[2]), "r"(a[3]), "r"(b[0]), "r"(b[1]));
}

// ---------------- tensor-core dual GEMM: [P | R] = X @ [Wl | Wr]^T (+b on R) ----
template <int LAYER, int BNH>
__global__ void __launch_bounds__(256)
gemm_dual_tc(const float* __restrict__ xin,
             const float* __restrict__ Wl, const float* __restrict__ Wr,
             const float* __restrict__ bias) {
    constexpr int K = KF, BM = 128, BN = 64, BK = 16, LD = BK + 4;
    __shared__ float sAh[BM][LD], sAl[BM][LD];
    __shared__ float sBh[BN][LD], sBl[BN][LD];

    const float* X = (LAYER == 1) ? xin : (const float*)g_h;
    const int tid = threadIdx.x;
    const int lane = tid & 31, wid = tid >> 5;
    const int wm = wid & 3, wn = wid >> 2;
    const int g = lane >> 2, t = lane & 3;
    const int row0 = blockIdx.x * BM;
    const int col0 = blockIdx.y * BN;

    float acc[2][4][4];
    #pragma unroll
    for (int mf = 0; mf < 2; mf++)
        #pragma unroll
        for (int nf = 0; nf < 4; nf++)
            #pragma unroll
            for (int i = 0; i < 4; i++) acc[mf][nf][i] = 0.f;

    for (int k0 = 0; k0 < K; k0 += BK) {
        #pragma unroll
        for (int i = 0; i < 2; i++) {
            int li = tid + i * 256;
            int r = li >> 2;
            int q = (li & 3) * 4;
            int gr = row0 + r;
            float4 v = (gr < NN) ? *(const float4*)&X[(size_t)gr * K + k0 + q]
                                 : make_float4(0.f, 0.f, 0.f, 0.f);
            float h0, l0, h1, l1, h2, l2, h3, l3;
            tf32split(v.x, h0, l0); tf32split(v.y, h1, l1);
            tf32split(v.z, h2, l2); tf32split(v.w, h3, l3);
            sAh[r][q] = h0; sAh[r][q + 1] = h1; sAh[r][q + 2] = h2; sAh[r][q + 3] = h3;
            sAl[r][q] = l0; sAl[r][q + 1] = l1; sAl[r][q + 2] = l2; sAl[r][q + 3] = l3;
        }
        {
            int r = tid >> 2;
            int q = (tid & 3) * 4;
            int c = col0 + r;
            const float* Wsrc = (c < BNH) ? &Wl[(size_t)c * K] : &Wr[(size_t)(c - BNH) * K];
            float4 v = *(const float4*)&Wsrc[k0 + q];
            float h0, l0, h1, l1, h2, l2, h3, l3;
            tf32split(v.x, h0, l0); tf32split(v.y, h1, l1);
            tf32split(v.z, h2, l2); tf32split(v.w, h3, l3);
            sBh[r][q] = h0; sBh[r][q + 1] = h1; sBh[r][q + 2] = h2; sBh[r][q + 3] = h3;
            sBl[r][q] = l0; sBl[r][q + 1] = l1; sBl[r][q + 2] = l2; sBl[r][q + 3] = l3;
        }
        __syncthreads();

        #pragma unroll
        for (int kk = 0; kk < BK; kk += 8) {
            uint32_t ah[2][4], al[2][4], bh[4][2], bl[4][2];
            #pragma unroll
            for (int mf = 0; mf < 2; mf++) {
                int rb = wm * 32 + mf * 16;
                ah[mf][0] = __float_as_uint(sAh[rb + g][kk + t]);
                ah[mf][1] = __float_as_uint(sAh[rb + g + 8][kk + t]);
                ah[mf][2] = __float_as_uint(sAh[rb + g][kk + t + 4]);
                ah[mf][3] = __float_as_uint(sAh[rb + g + 8][kk + t + 4]);
                al[mf][0] = __float_as_uint(sAl[rb + g][kk + t]);
                al[mf][1] = __float_as_uint(sAl[rb + g + 8][kk + t]);
                al[mf][2] = __float_as_uint(sAl[rb + g][kk + t + 4]);
                al[mf][3] = __float_as_uint(sAl[rb + g + 8][kk + t + 4]);
            }
            #pragma unroll
            for (int nf = 0; nf < 4; nf++) {
                int nb = wn * 32 + nf * 8;
                bh[nf][0] = __float_as_uint(sBh[nb + g][kk + t]);
                bh[nf][1] = __float_as_uint(sBh[nb + g][kk + t + 4]);
                bl[nf][0] = __float_as_uint(sBl[nb + g][kk + t]);
                bl[nf][1] = __float_as_uint(sBl[nb + g][kk + t + 4]);
            }
            #pragma unroll
            for (int mf = 0; mf < 2; mf++)
                #pragma unroll
                for (int nf = 0; nf < 4; nf++) {
                    mma_tf32(acc[mf][nf], ah[mf], bh[nf]);
                    mma_tf32(acc[mf][nf], ah[mf], bl[nf]);
                    mma_tf32(acc[mf][nf], al[mf], bh[nf]);
                }
        }
        __syncthreads();
    }

    const bool isP = (col0 < BNH);
    float* dstb = isP ? (float*)g_p : (float*)g_r;
    const int cb = col0 - (isP ? 0 : BNH);
    #pragma unroll
    for (int nf = 0; nf < 4; nf++) {
        int c = cb + wn * 32 + nf * 8 + 2 * t;
        float b0v = isP ? 0.f : bias[c];
        float b1v = isP ? 0.f : bias[c + 1];
        #pragma unroll
        for (int mf = 0; mf < 2; mf++) {
            int r = row0 + wm * 32 + mf * 16 + g;
            if (r < NN) {
                float2 o = make_float2(acc[mf][nf][0] + b0v, acc[mf][nf][1] + b1v);
                *(float2*)&dstb[(size_t)r * BNH + c] = o;
            }
            if (r + 8 < NN) {
                float2 o = make_float2(acc[mf][nf][2] + b0v, acc[mf][nf][3] + b1v);
                *(float2*)&dstb[(size_t)(r + 8) * BNH + c] = o;
            }
        }
    }
}

// ---------------- fused aggregation epilogues -----------------------------------
__global__ void agg128_relu_kernel() {
    int v = blockIdx.x * (blockDim.x >> 5) + (threadIdx.x >> 5);
    if (v >= NN) return;
    int lane = threadIdx.x & 31;
    const float* P = (const float*)g_p;
    int beg = g_off[v], end = g_off[v + 1];
    float4 acc = make_float4(0.f, 0.f, 0.f, 0.f);
    int j = beg;
    for (; j + 3 < end; j += 4) {
        int s0 = g_csrc[j], s1 = g_csrc[j + 1], s2 = g_csrc[j + 2], s3 = g_csrc[j + 3];
        float4 t0 = ((const float4*)(P + (size_t)s0 * 128))[lane];
        float4 t1 = ((const float4*)(P + (size_t)s1 * 128))[lane];
        float4 t2 = ((const float4*)(P + (size_t)s2 * 128))[lane];
        float4 t3 = ((const float4*)(P + (size_t)s3 * 128))[lane];
        acc.x += (t0.x + t1.x) + (t2.x + t3.x);
        acc.y += (t0.y + t1.y) + (t2.y + t3.y);
        acc.z += (t0.z + t1.z) + (t2.z + t3.z);
        acc.w += (t0.w + t1.w) + (t2.w + t3.w);
    }
    for (; j < end; j++) {
        int s = g_csrc[j];
        float4 t = ((const float4*)(P + (size_t)s * 128))[lane];
        acc.x += t.x; acc.y += t.y; acc.z += t.z; acc.w += t.w;
    }
    float rc = g_rcnt[v];
    float4 rr = ((const float4*)(g_r + (size_t)v * 128))[lane];
    float4 o;
    o.x = fmaxf(fmaf(acc.x, rc, rr.x), 0.f);
    o.y = fmaxf(fmaf(acc.y, rc, rr.y), 0.f);
    o.z = fmaxf(fmaf(acc.z, rc, rr.z), 0.f);
    o.w = fmaxf(fmaf(acc.w, rc, rr.w), 0.f);
    ((float4*)(g_h + (size_t)v * 128))[lane] = o;
}

// h2s[v] = dis[v] * (rcnt[v]*AggSum(P2) + R2[v])   -- pre-scaled for iconv
__global__ void agg64_kernel() {
    int v = blockIdx.x * (blockDim.x >> 5) + (threadIdx.x >> 5);
    if (v >= NN) return;
    int lane = threadIdx.x & 31;
    const float* P = (const float*)g_p;   // stride 64
    int beg = g_off[v], end = g_off[v + 1];
    float ax = 0.f, ay = 0.f;
    int j = beg;
    for (; j + 3 < end; j += 4) {
        int s0 = g_csrc[j], s1 = g_csrc[j + 1], s2 = g_csrc[j + 2], s3 = g_csrc[j + 3];
        float2 t0 = ((const float2*)(P + (size_t)s0 * 64))[lane];
        float2 t1 = ((const float2*)(P + (size_t)s1 * 64))[lane];
        float2 t2 = ((const float2*)(P + (size_t)s2 * 64))[lane];
        float2 t3 = ((const float2*)(P + (size_t)s3 * 64))[lane];
        ax += (t0.x + t1.x) + (t2.x + t3.x);
        ay += (t0.y + t1.y) + (t2.y + t3.y);
    }
    for (; j < end; j++) {
        int s = g_csrc[j];
        float2 t = ((const float2*)(P + (size_t)s * 64))[lane];
        ax += t.x; ay += t.y;
    }
    float rc = g_rcnt[v];
    float dv = g_dis[v];
    float2 rr = ((const float2*)(g_r + (size_t)v * 64))[lane];
    float2 o;
    o.x = dv * fmaf(ax, rc, rr.x);
    o.y = dv * fmaf(ay, rc, rr.y);
    ((float2*)(g_h2 + (size_t)v * 64))[lane] = o;
}

// out[v] = dis[v] * (sum_e h2s[src] + h2s[v])      -- pure gather-sum
__global__ void iconv_kernel(float* __restrict__ out) {
    int v = blockIdx.x * (blockDim.x >> 5) + (threadIdx.x >> 5);
    if (v >= NN) return;
    const float* h2 = (const float*)g_h2;
    int lane = threadIdx.x & 31;
    float2 hv = ((const float2*)(h2 + (size_t)v * 64))[lane];
    float accx = hv.x, accy = hv.y;
    int beg = g_off[v], end = g_off[v + 1];
    int j = beg;
    for (; j + 3 < end; j += 4) {
        int s0 = g_csrc[j], s1 = g_csrc[j + 1], s2 = g_csrc[j + 2], s3 = g_csrc[j + 3];
        float2 t0 = ((const float2*)(h2 + (size_t)s0 * 64))[lane];
        float2 t1 = ((const float2*)(h2 + (size_t)s1 * 64))[lane];
        float2 t2 = ((const float2*)(h2 + (size_t)s2 * 64))[lane];
        float2 t3 = ((const float2*)(h2 + (size_t)s3 * 64))[lane];
        accx += (t0.x + t1.x) + (t2.x + t3.x);
        accy += (t0.y + t1.y) + (t2.y + t3.y);
    }
    for (; j < end; j++) {
        int s = g_csrc[j];
        float2 t = ((const float2*)(h2 + (size_t)s * 64))[lane];
        accx += t.x; accy += t.y;
    }
    float dv = g_dis[v];
    float2 r;
    r.x = dv * accx;
    r.y = dv * accy;
    ((float2*)(out + (size_t)v * 64))[lane] = r;
}

// ---------------- launcher ------------------------------------------------------
extern "C" void kernel_launch(void* const* d_in, const int* in_sizes, int n_in,
                              void* d_out, int out_size) {
    const float* x   = (const float*)d_in[0];
    const int*   ei  = (const int*)d_in[1];   // int32 (JAX x64 disabled)
    const float* W1l = (const float*)d_in[2];
    const float* b1  = (const float*)d_in[3];
    const float* W1r = (const float*)d_in[4];
    const float* W2l = (const float*)d_in[5];
    const float* b2  = (const float*)d_in[6];
    const float* W2r = (const float*)d_in[7];
    float* out = (float*)d_out;

    const int* src = ei;
    const int* dst = ei + EE;

    static cudaStream_t s_side = nullptr;
    static cudaEvent_t ev_fork = nullptr, ev_join = nullptr, ev_csr = nullptr, ev_zero = nullptr;
    static bool tried = false;
    if (!tried) {
        tried = true;
        bool ok = cudaStreamCreateWithFlags(&s_side, cudaStreamNonBlocking) == cudaSuccess &&
                  cudaEventCreateWithFlags(&ev_fork, cudaEventDisableTiming) == cudaSuccess &&
                  cudaEventCreateWithFlags(&ev_join, cudaEventDisableTiming) == cudaSuccess &&
                  cudaEventCreateWithFlags(&ev_csr,  cudaEventDisableTiming) == cudaSuccess &&
                  cudaEventCreateWithFlags(&ev_zero, cudaEventDisableTiming) == cudaSuccess;
        if (!ok) s_side = nullptr;
    }

    const int NB = (NN + 255) / 256;
    const int E4B = (EE / 4 + 255) / 256;
    const int WARP_GRID = (NN + 7) / 8;
    const dim3 G1((NN + 127) / 128, 4);   // N2 = 256
    const dim3 G2((NN + 127) / 128, 2);   // N2 = 128

    if (s_side) {
        // fork: GEMM1 on side stream, CSR chain on main
        cudaEventRecord(ev_fork, 0);
        cudaStreamWaitEvent(s_side, ev_fork, 0);
        gemm_dual_tc<1, 128><<<G1, 256, 0, s_side>>>(x, W1l, W1r, b1);
        cudaEventRecord(ev_join, s_side);

        count_deg_kernel<<<E4B, 256>>>((const int4*)dst);
        scanA_kernel<<<SCAN_BLK, 1024>>>();
        scanC_kernel<<<NB, 256>>>();
        // g_deg no longer needed after scanC: re-zero it for the next replay,
        // overlapped on the side stream (after GEMM1 completes there).
        cudaEventRecord(ev_csr, 0);
        cudaStreamWaitEvent(s_side, ev_csr, 0);
        zero_deg_kernel<<<NB, 256, 0, s_side>>>();
        cudaEventRecord(ev_zero, s_side);

        build_csr_kernel<<<E4B, 256>>>((const int4*)src, (const int4*)dst);
        cudaStreamWaitEvent(0, ev_join, 0);   // g_p/g_r ready

        agg128_relu_kernel<<<WARP_GRID, 256>>>();
        gemm_dual_tc<2, 64><<<G2, 256>>>(x, W2l, W2r, b2);
        agg64_kernel<<<WARP_GRID, 256>>>();
        iconv_kernel<<<WARP_GRID, 256>>>(out);

        cudaStreamWaitEvent(0, ev_zero, 0);   // join side work before capture end
    } else {
        zero_deg_kernel<<<NB, 256>>>();       // sequential fallback: zero up front
        count_deg_kernel<<<E4B, 256>>>((const int4*)dst);
        scanA_kernel<<<SCAN_BLK, 1024>>>();
        scanC_kernel<<<NB, 256>>>();
        build_csr_kernel<<<E4B, 256>>>((const int4*)src, (const int4*)dst);
        gemm_dual_tc<1, 128><<<G1, 256>>>(x, W1l, W1r, b1);
        agg128_relu_kernel<<<WARP_GRID, 256>>>();
        gemm_dual_tc<2, 64><<<G2, 256>>>(x, W2l, W2r, b2);
        agg64_kernel<<<WARP_GRID, 256>>>();
        iconv_kernel<<<WARP_GRID, 256>>>(out);
    }
}